// round 3
// baseline (speedup 1.0000x reference)
#include <cuda_runtime.h>
#include <cuda_bf16.h>
#include <math.h>

#define NB 32
#define DIM 4096
#define NKV 8
#define NREP 4
#define HD 128
#define MAXSEQ 2048
#define NCHUNK 8
#define CHUNK 256
#define QKV_SPLIT 8
#define O_SPLIT 8

// ------------------------- device scratch (no allocs allowed) ---------------
__device__ float g_q[NB * DIM];                          // rope'd Q
__device__ float g_k[NB * NKV * HD];                     // rope'd new K row
__device__ float g_v[NB * NKV * HD];                     // new V row
__device__ float g_attn[NB * DIM];                       // attention output
__device__ float g_part[QKV_SPLIT * NB * 6144];          // split-K partials
__device__ float g_pout[NB * NKV * NREP * NCHUNK * HD];  // attn partial outs
__device__ float g_ml[NB * NKV * NREP * NCHUNK * 2];     // (m, l) per chunk

// ------------------------- bf16x3 MMA projection GEMM -----------------------
// out_part[split][b][j] = sum_{k in split} A[b][k] * W[j][k]
// A: 32 x 4096 row-major. W: rows x 4096 row-major (j-major, k contiguous).
// Block: 128 threads (4 warps). Block tile: M=32, N=128. Warp: M=32 x N=32.
// K-chunk = 64 (4 k16 steps). mma.sync.m16n8k16 bf16, 3 mma per tile
// (hi*hi + lo*hi + hi*lo) for ~fp32 accuracy.
//
// smem frag-packed layouts:
//  sB[(nt*4+ks)*144 + lane*4 + {b0h,b0l,b1h,b1l}]  (nt=0..15, ks=0..3)
//  sAh/sAl[((mt*4+ks))*132 + lane*4 + {a0,a1,a2,a3}]

#define MMA_B16(acc, A0, A1, A2, A3, B0, B1)                                   \
    asm volatile(                                                              \
        "mma.sync.aligned.m16n8k16.row.col.f32.bf16.bf16.f32 "                 \
        "{%0,%1,%2,%3}, {%4,%5,%6,%7}, {%8,%9}, {%0,%1,%2,%3};"                \
        : "+f"(acc[0]), "+f"(acc[1]), "+f"(acc[2]), "+f"(acc[3])               \
        : "r"(A0), "r"(A1), "r"(A2), "r"(A3), "r"(B0), "r"(B1))

__device__ __forceinline__ void bf16_split(float v, unsigned& hbits, unsigned& lbits)
{
    __nv_bfloat16 h = __float2bfloat16_rn(v);
    float r = v - __bfloat162float(h);
    __nv_bfloat16 lo = __float2bfloat16_rn(r);
    hbits = (unsigned)__bfloat16_as_ushort(h);
    lbits = (unsigned)__bfloat16_as_ushort(lo);
}

__global__ __launch_bounds__(128) void proj_mma(
    const float* __restrict__ A,   // NB x 4096 (nullptr -> g_attn)
    const float* __restrict__ W0,
    const float* __restrict__ W1,
    const float* __restrict__ W2,
    int njb, int r1, int r2, int klen, int totalj)
{
    __shared__ unsigned sB[16 * 4 * 144];   // 36 KB
    __shared__ unsigned sAh[2 * 4 * 132];   // 4.2 KB
    __shared__ unsigned sAl[2 * 4 * 132];   // 4.2 KB

    const float* Ap = A ? A : g_attn;

    int jb    = blockIdx.x % njb;
    int split = blockIdx.x / njb;
    int j0    = jb * 128;

    const float* W;
    int jw;
    if (j0 < r1)      { W = W0; jw = j0; }
    else if (j0 < r2) { W = W1; jw = j0 - r1; }
    else              { W = W2; jw = j0 - r2; }

    int tid = threadIdx.x;
    int w   = tid >> 5, l = tid & 31;

    float acc[2][4][4];
#pragma unroll
    for (int i = 0; i < 2; i++)
#pragma unroll
        for (int j = 0; j < 4; j++)
#pragma unroll
            for (int c = 0; c < 4; c++) acc[i][j][c] = 0.f;

    int k0 = split * klen;
    int ksw   = l >> 3;            // k16-step this lane's pair falls in
    int prw   = (l >> 2) & 1;      // b0/b1 (or a k-high) selector
    int lq    = l & 3;

    for (int kc = k0; kc < k0 + klen; kc += 64) {
        __syncthreads();
        // ---- stage W tile: warp w handles block-rows [32w, 32w+32) --------
#pragma unroll 4
        for (int rr = 0; rr < 32; rr++) {
            int n = w * 32 + rr;
            float2 v = *(const float2*)(W + (size_t)(jw + n) * 4096 + kc + 2 * l);
            unsigned h0, l0, h1, l1;
            bf16_split(v.x, h0, l0);
            bf16_split(v.y, h1, l1);
            unsigned uh = (h1 << 16) | h0;
            unsigned ul = (l1 << 16) | l0;
            int nt = n >> 3;
            int lanep = ((n & 7) << 2) + lq;
            *(uint2*)&sB[((nt * 4 + ksw) * 144) + lanep * 4 + prw * 2] =
                make_uint2(uh, ul);
        }
        // ---- stage A tile: warp w handles rows [8w, 8w+8) -----------------
#pragma unroll
        for (int rr = 0; rr < 8; rr++) {
            int m = w * 8 + rr;
            float2 v = *(const float2*)(Ap + (size_t)m * 4096 + kc + 2 * l);
            unsigned h0, l0, h1, l1;
            bf16_split(v.x, h0, l0);
            bf16_split(v.y, h1, l1);
            unsigned uh = (h1 << 16) | h0;
            unsigned ul = (l1 << 16) | l0;
            int mt = m >> 4;
            int lanep = ((m & 7) << 2) + lq;
            int anum  = ((m >> 3) & 1) | (prw << 1);
            int idx = (mt * 4 + ksw) * 132 + lanep * 4 + anum;
            sAh[idx] = uh;
            sAl[idx] = ul;
        }
        __syncthreads();

        // ---- compute ------------------------------------------------------
#pragma unroll
        for (int ks = 0; ks < 4; ks++) {
            uint4 ah0 = *(const uint4*)&sAh[(ks) * 132 + l * 4];
            uint4 al0 = *(const uint4*)&sAl[(ks) * 132 + l * 4];
            uint4 ah1 = *(const uint4*)&sAh[(4 + ks) * 132 + l * 4];
            uint4 al1 = *(const uint4*)&sAl[(4 + ks) * 132 + l * 4];
#pragma unroll
            for (int ntl = 0; ntl < 4; ntl++) {
                uint4 bb = *(const uint4*)&sB[((w * 4 + ntl) * 4 + ks) * 144 + l * 4];
                // hi*hi
                MMA_B16(acc[0][ntl], ah0.x, ah0.y, ah0.z, ah0.w, bb.x, bb.z);
                MMA_B16(acc[1][ntl], ah1.x, ah1.y, ah1.z, ah1.w, bb.x, bb.z);
                // lo*hi
                MMA_B16(acc[0][ntl], al0.x, al0.y, al0.z, al0.w, bb.x, bb.z);
                MMA_B16(acc[1][ntl], al1.x, al1.y, al1.z, al1.w, bb.x, bb.z);
                // hi*lo
                MMA_B16(acc[0][ntl], ah0.x, ah0.y, ah0.z, ah0.w, bb.y, bb.w);
                MMA_B16(acc[1][ntl], ah1.x, ah1.y, ah1.z, ah1.w, bb.y, bb.w);
            }
        }
    }

    // ---- epilogue: write split partials ----------------------------------
    size_t pbase = (size_t)split * NB * totalj;
#pragma unroll
    for (int mt = 0; mt < 2; mt++)
#pragma unroll
        for (int ntl = 0; ntl < 4; ntl++) {
            int m = mt * 16 + (l >> 2);
            int j = j0 + ((w * 4 + ntl) << 3) + (lq << 1);
            *(float2*)&g_part[pbase + (size_t)m * totalj + j] =
                make_float2(acc[mt][ntl][0], acc[mt][ntl][1]);
            *(float2*)&g_part[pbase + (size_t)(m + 8) * totalj + j] =
                make_float2(acc[mt][ntl][2], acc[mt][ntl][3]);
        }
}

// ------------------------- split-K reduce + RoPE ----------------------------
__global__ void qkv_finish(const float* __restrict__ fc, const float* __restrict__ fs)
{
    int p = blockIdx.x * blockDim.x + threadIdx.x;  // pair index, 32*3072 total
    if (p >= NB * 3072) return;
    int b = p / 3072;
    int j = (p % 3072) * 2;

    float v0 = 0.f, v1 = 0.f;
#pragma unroll
    for (int s = 0; s < QKV_SPLIT; s++) {
        size_t base = (size_t)s * NB * 6144 + (size_t)b * 6144 + j;
        v0 += g_part[base];
        v1 += g_part[base + 1];
    }

    if (j < 5120) {
        int pi = (j & 127) >> 1;
        float c = fc[pi], s = fs[pi];
        float o0 = v0 * c - v1 * s;
        float o1 = v0 * s + v1 * c;
        if (j < 4096) {
            g_q[b * DIM + j]     = o0;
            g_q[b * DIM + j + 1] = o1;
        } else {
            g_k[b * 1024 + j - 4096]     = o0;
            g_k[b * 1024 + j - 4096 + 1] = o1;
        }
    } else {
        g_v[b * 1024 + j - 5120]     = v0;
        g_v[b * 1024 + j - 5120 + 1] = v1;
    }
}

// ------------------------- flash-decode attention ---------------------------
__global__ __launch_bounds__(128) void attn_kernel(
    const float* __restrict__ cache_k, const float* __restrict__ cache_v,
    const int* __restrict__ sp)
{
    int blk = blockIdx.x;                 // c + 8*(h + 8*b)
    int c = blk & 7;
    int h = (blk >> 3) & 7;
    int b = blk >> 6;

    int tid = threadIdx.x;
    int w = tid >> 5, lane = tid & 31;

    int start_pos = *sp;
    int t_total = start_pos + 1;

    __shared__ float qs[4][HD];           // scaled q
    __shared__ float ks[32][132];         // K tile
    __shared__ float sc[CHUNK][4];        // scores -> probs
    __shared__ float red[4][4][HD];       // warp x rep x d

    const float scale = 0.08838834764831845f;  // 1/sqrt(128)
    for (int i = tid; i < 4 * HD; i += 128) {
        int r = i >> 7, d = i & 127;
        qs[r][d] = g_q[(size_t)b * DIM + (h * NREP + r) * HD + d] * scale;
    }

    int tbase = c * CHUNK;

    // phase 1: scores, 8 tiles of 32 rows
    for (int tile = 0; tile < 8; tile++) {
        int trow0 = tbase + tile * 32;
        __syncthreads();
#pragma unroll
        for (int jj = 0; jj < 8; jj++) {
            int idx = tid + 128 * jj;
            int row = idx >> 5, q4 = idx & 31;
            int tpos = trow0 + row;
            float4 val = make_float4(0.f, 0.f, 0.f, 0.f);
            if (tpos < t_total) {
                const float* krow = (tpos == start_pos)
                    ? &g_k[(size_t)b * 1024 + h * HD]
                    : &cache_k[(((size_t)b * MAXSEQ + tpos) * NKV + h) * HD];
                val = *(const float4*)(krow + q4 * 4);
            }
            *(float4*)&ks[row][q4 * 4] = val;
        }
        __syncthreads();
        int tpos = trow0 + lane;
        float s = 0.f;
#pragma unroll 8
        for (int dq = 0; dq < 32; dq++) {
            float4 k4 = *(const float4*)&ks[lane][dq * 4];
            float4 q4 = *(const float4*)&qs[w][dq * 4];
            s += k4.x * q4.x + k4.y * q4.y + k4.z * q4.z + k4.w * q4.w;
        }
        sc[tile * 32 + lane][w] = (tpos < t_total) ? s : -INFINITY;
    }
    __syncthreads();

    // phase 2: partial softmax, warp w handles rep r = w
    {
        int r = w;
        float sv[NCHUNK];
        float m = -INFINITY;
#pragma unroll
        for (int i = 0; i < 8; i++) {
            sv[i] = sc[lane + 32 * i][r];
            m = fmaxf(m, sv[i]);
        }
#pragma unroll
        for (int off = 16; off > 0; off >>= 1)
            m = fmaxf(m, __shfl_xor_sync(0xffffffffu, m, off));
        float lsum = 0.f;
#pragma unroll
        for (int i = 0; i < 8; i++) {
            float p = (m == -INFINITY) ? 0.f : __expf(sv[i] - m);
            sc[lane + 32 * i][r] = p;
            lsum += p;
        }
#pragma unroll
        for (int off = 16; off > 0; off >>= 1)
            lsum += __shfl_xor_sync(0xffffffffu, lsum, off);
        if (lane == 0) {
            size_t mlidx = ((((size_t)b * NKV + h) * NREP + r) * NCHUNK + c) * 2;
            g_ml[mlidx]     = m;
            g_ml[mlidx + 1] = lsum;
        }
    }
    __syncthreads();

    // phase 3: p @ V (coalesced V reads, lane owns d-quad)
    float4 acc0 = make_float4(0, 0, 0, 0), acc1 = acc0, acc2 = acc0, acc3 = acc0;
    for (int i = 0; i < 64; i++) {
        int tl = w * 64 + i;
        int tpos = tbase + tl;
        if (tpos >= t_total) break;
        const float* vrow = (tpos == start_pos)
            ? &g_v[(size_t)b * 1024 + h * HD]
            : &cache_v[(((size_t)b * MAXSEQ + tpos) * NKV + h) * HD];
        float4 vv = *(const float4*)(vrow + lane * 4);
        float4 p = *(const float4*)&sc[tl][0];
        acc0.x += p.x * vv.x; acc0.y += p.x * vv.y; acc0.z += p.x * vv.z; acc0.w += p.x * vv.w;
        acc1.x += p.y * vv.x; acc1.y += p.y * vv.y; acc1.z += p.y * vv.z; acc1.w += p.y * vv.w;
        acc2.x += p.z * vv.x; acc2.y += p.z * vv.y; acc2.z += p.z * vv.z; acc2.w += p.z * vv.w;
        acc3.x += p.w * vv.x; acc3.y += p.w * vv.y; acc3.z += p.w * vv.z; acc3.w += p.w * vv.w;
    }
    *(float4*)&red[w][0][lane * 4] = acc0;
    *(float4*)&red[w][1][lane * 4] = acc1;
    *(float4*)&red[w][2][lane * 4] = acc2;
    *(float4*)&red[w][3][lane * 4] = acc3;
    __syncthreads();

    for (int i = tid; i < 4 * HD; i += 128) {
        int r = i >> 7, d = i & 127;
        float v = red[0][r][d] + red[1][r][d] + red[2][r][d] + red[3][r][d];
        g_pout[(((((size_t)b * NKV + h) * NREP + r) * NCHUNK) + c) * HD + d] = v;
    }
}

// ------------------------- combine partial softmax --------------------------
__global__ __launch_bounds__(128) void combine_kernel()
{
    int blk = blockIdx.x;                 // r + 4*(h + 8*b)
    int r = blk & 3;
    int h = (blk >> 2) & 7;
    int b = blk >> 5;
    int d = threadIdx.x;

    size_t base = (((size_t)b * NKV + h) * NREP + r) * NCHUNK;

    float mm[NCHUNK], ll[NCHUNK];
    float mg = -INFINITY;
#pragma unroll
    for (int c = 0; c < NCHUNK; c++) {
        mm[c] = g_ml[(base + c) * 2];
        ll[c] = g_ml[(base + c) * 2 + 1];
        if (ll[c] > 0.f) mg = fmaxf(mg, mm[c]);
    }
    float L = 0.f, o = 0.f;
#pragma unroll
    for (int c = 0; c < NCHUNK; c++) {
        if (ll[c] > 0.f) {
            float f = __expf(mm[c] - mg);
            L += ll[c] * f;
            o += f * g_pout[(base + c) * HD + d];
        }
    }
    g_attn[(size_t)b * DIM + (h * NREP + r) * HD + d] = o / L;
}

// ------------------------- O-proj split-K reduce ----------------------------
__global__ void o_finish(float* __restrict__ out)
{
    int i = blockIdx.x * blockDim.x + threadIdx.x;  // 32768 float4 elems
    if (i >= NB * DIM / 4) return;
    float4 s = make_float4(0.f, 0.f, 0.f, 0.f);
#pragma unroll
    for (int p = 0; p < O_SPLIT; p++) {
        float4 v = *((const float4*)&g_part[(size_t)p * NB * DIM] + i);
        s.x += v.x; s.y += v.y; s.z += v.z; s.w += v.w;
    }
    ((float4*)out)[i] = s;
}

// ------------------------- launcher -----------------------------------------
extern "C" void kernel_launch(void* const* d_in, const int* in_sizes, int n_in,
                              void* d_out, int out_size)
{
    const float* x  = (const float*)d_in[0];
    const float* fc = (const float*)d_in[1];
    const float* fs = (const float*)d_in[2];
    const float* wq = (const float*)d_in[3];
    const float* wk = (const float*)d_in[4];
    const float* wv = (const float*)d_in[5];
    const float* wo = (const float*)d_in[6];
    const float* ck = (const float*)d_in[7];
    const float* cv = (const float*)d_in[8];
    const int*   sp = (const int*)d_in[9];
    float* out = (float*)d_out;

    // QKV projection: 6144 cols, 48 n-slabs x split 8 = 384 blocks
    proj_mma<<<48 * QKV_SPLIT, 128>>>(x, wq, wk, wv, 48, 4096, 5120,
                                      4096 / QKV_SPLIT, 6144);
    qkv_finish<<<384, 256>>>(fc, fs);
    attn_kernel<<<2048, 128>>>(ck, cv, sp);
    combine_kernel<<<1024, 128>>>();
    // O projection: 4096 cols, 32 n-slabs x split 8 = 256 blocks
    proj_mma<<<32 * O_SPLIT, 128>>>(nullptr, wo, wo, wo, 32, 4096, 8192,
                                    4096 / O_SPLIT, 4096);
    o_finish<<<128, 256>>>(out);
}

// round 4
// speedup vs baseline: 1.3743x; 1.3743x over previous
#include <cuda_runtime.h>
#include <math.h>

#define NB 32
#define DIM 4096
#define NKV 8
#define NREP 4
#define HD 128
#define MAXSEQ 2048
#define NCHUNK 8
#define CHUNK 256
#define QKV_SPLIT 4
#define O_SPLIT 8

// ------------------------- device scratch (no allocs allowed) ---------------
__device__ float g_q[NB * DIM];                          // rope'd Q
__device__ float g_k[NB * NKV * HD];                     // rope'd new K row
__device__ float g_v[NB * NKV * HD];                     // new V row
__device__ float g_attn[NB * DIM];                       // attention output
__device__ float g_part[O_SPLIT * NB * 6144];            // split-K partials
__device__ float g_pout[NB * NKV * NREP * NCHUNK * HD];  // attn partial outs
__device__ float g_ml[NB * NKV * NREP * NCHUNK * 2];     // (m, l) per chunk

// ------------------------- projection GEMM (fp32 SIMT) ----------------------
__global__ __launch_bounds__(128) void proj_kernel(
    const float* __restrict__ A,   // NB x 4096 activations (nullptr -> g_attn)
    const float* __restrict__ W0,
    const float* __restrict__ W1,
    const float* __restrict__ W2,
    int njb, int r1, int r2, int klen, int totalj)
{
    __shared__ float As[32][68];
    __shared__ float Ws[64][68];

    const float* Ap = A ? A : g_attn;

    int jb    = blockIdx.x % njb;
    int split = blockIdx.x / njb;
    int j0    = jb * 64;

    const float* W;
    int jw;
    if (j0 < r1)      { W = W0; jw = j0; }
    else if (j0 < r2) { W = W1; jw = j0 - r1; }
    else              { W = W2; jw = j0 - r2; }

    int tid = threadIdx.x;
    int jj  = tid & 15;
    int bg  = tid >> 4;

    int k0 = split * klen;

    float acc[4][4];
#pragma unroll
    for (int i = 0; i < 4; i++)
#pragma unroll
        for (int j = 0; j < 4; j++) acc[i][j] = 0.f;

    for (int kc = k0; kc < k0 + klen; kc += 64) {
        __syncthreads();
#pragma unroll
        for (int i = 0; i < 4; i++) {
            int s = tid + 128 * i;
            int bb = s >> 4, kq = s & 15;
            *(float4*)&As[bb][kq * 4] =
                *(const float4*)&Ap[(size_t)bb * 4096 + kc + kq * 4];
        }
#pragma unroll
        for (int i = 0; i < 8; i++) {
            int s = tid + 128 * i;
            int row = s >> 4, kq = s & 15;
            *(float4*)&Ws[row][kq * 4] =
                *(const float4*)&W[(size_t)(jw + row) * 4096 + kc + kq * 4];
        }
        __syncthreads();

#pragma unroll 4
        for (int kk = 0; kk < 64; kk += 4) {
            float4 a4[4], w4[4];
#pragma unroll
            for (int ib = 0; ib < 4; ib++)
                a4[ib] = *(const float4*)&As[bg + 8 * ib][kk];
#pragma unroll
            for (int ii = 0; ii < 4; ii++)
                w4[ii] = *(const float4*)&Ws[jj + 16 * ii][kk];
#pragma unroll
            for (int ib = 0; ib < 4; ib++)
#pragma unroll
                for (int ii = 0; ii < 4; ii++)
                    acc[ib][ii] += a4[ib].x * w4[ii].x + a4[ib].y * w4[ii].y +
                                   a4[ib].z * w4[ii].z + a4[ib].w * w4[ii].w;
        }
    }

#pragma unroll
    for (int ib = 0; ib < 4; ib++)
#pragma unroll
        for (int ii = 0; ii < 4; ii++) {
            int b = bg + 8 * ib;
            int j = j0 + jj + 16 * ii;
            g_part[(size_t)split * NB * totalj + (size_t)b * totalj + j] = acc[ib][ii];
        }
}

// ------------------------- split-K reduce + RoPE ----------------------------
__global__ void qkv_finish(const float* __restrict__ fc, const float* __restrict__ fs)
{
    int p = blockIdx.x * blockDim.x + threadIdx.x;
    if (p >= NB * 3072) return;
    int b = p / 3072;
    int j = (p % 3072) * 2;

    float v0 = 0.f, v1 = 0.f;
#pragma unroll
    for (int s = 0; s < QKV_SPLIT; s++) {
        size_t base = (size_t)s * NB * 6144 + (size_t)b * 6144 + j;
        v0 += g_part[base];
        v1 += g_part[base + 1];
    }

    if (j < 5120) {
        int pi = (j & 127) >> 1;
        float c = fc[pi], s = fs[pi];
        float o0 = v0 * c - v1 * s;
        float o1 = v0 * s + v1 * c;
        if (j < 4096) {
            g_q[b * DIM + j]     = o0;
            g_q[b * DIM + j + 1] = o1;
        } else {
            g_k[b * 1024 + j - 4096]     = o0;
            g_k[b * 1024 + j - 4096 + 1] = o1;
        }
    } else {
        g_v[b * 1024 + j - 5120]     = v0;
        g_v[b * 1024 + j - 5120 + 1] = v1;
    }
}

// ------------------------- flash-decode attention ---------------------------
// One block per (b, kv_head, chunk). 128 threads = 4 warps.
// BOTH K and V streams are smem-staged (MLP=8 per thread) with double
// buffering: prefetch next 32-row tile into regs, compute current from smem,
// store regs into alternate buffer, one __syncthreads per tile.
__global__ __launch_bounds__(128) void attn_kernel(
    const float* __restrict__ cache_k, const float* __restrict__ cache_v,
    const int* __restrict__ sp)
{
    int blk = blockIdx.x;                 // c + 8*(h + 8*b)
    int c = blk & 7;
    int h = (blk >> 3) & 7;
    int b = blk >> 6;

    int tid = threadIdx.x;
    int w = tid >> 5, lane = tid & 31;

    int start_pos = *sp;
    int t_total = start_pos + 1;

    __shared__ float qs[4][HD];           // scaled q, 2KB
    __shared__ float ts[2][32][132];      // staged K/V tiles, 33.8KB
    __shared__ float sc[CHUNK][4];        // scores -> probs, 4KB

    const float scale = 0.08838834764831845f;  // 1/sqrt(128)
    for (int i = tid; i < 4 * HD; i += 128) {
        int r = i >> 7, d = i & 127;
        qs[r][d] = g_q[(size_t)b * DIM + (h * NREP + r) * HD + d] * scale;
    }

    int tbase = c * CHUNK;

    // thread's staging slots: rows w+4*jj, column-quad = lane
    float4 pre[8];

    // ======================= phase 1: scores (K stream) =====================
    // prefetch tile 0
#pragma unroll
    for (int jj = 0; jj < 8; jj++) {
        int row = w + 4 * jj;
        int tpos = tbase + row;
        float4 val = make_float4(0.f, 0.f, 0.f, 0.f);
        if (tpos < t_total) {
            const float* krow = (tpos == start_pos)
                ? &g_k[(size_t)b * 1024 + h * HD]
                : &cache_k[(((size_t)b * MAXSEQ + tpos) * NKV + h) * HD];
            val = *(const float4*)(krow + lane * 4);
        }
        pre[jj] = val;
    }
#pragma unroll
    for (int jj = 0; jj < 8; jj++)
        *(float4*)&ts[0][w + 4 * jj][lane * 4] = pre[jj];
    __syncthreads();

    int buf = 0;
    for (int tile = 0; tile < 8; tile++) {
        // prefetch next tile (LDG issued before compute -> overlapped)
        if (tile < 7) {
            int trow0 = tbase + (tile + 1) * 32;
#pragma unroll
            for (int jj = 0; jj < 8; jj++) {
                int tpos = trow0 + w + 4 * jj;
                float4 val = make_float4(0.f, 0.f, 0.f, 0.f);
                if (tpos < t_total) {
                    const float* krow = (tpos == start_pos)
                        ? &g_k[(size_t)b * 1024 + h * HD]
                        : &cache_k[(((size_t)b * MAXSEQ + tpos) * NKV + h) * HD];
                    val = *(const float4*)(krow + lane * 4);
                }
                pre[jj] = val;
            }
        }
        // compute: warp w -> rep w; lane -> row lane of current tile
        {
            int tpos = tbase + tile * 32 + lane;
            float s = 0.f;
#pragma unroll 8
            for (int dq = 0; dq < 32; dq++) {
                float4 k4 = *(const float4*)&ts[buf][lane][dq * 4];
                float4 q4 = *(const float4*)&qs[w][dq * 4];
                s += k4.x * q4.x + k4.y * q4.y + k4.z * q4.z + k4.w * q4.w;
            }
            sc[tile * 32 + lane][w] = (tpos < t_total) ? s : -INFINITY;
        }
        if (tile < 7) {
#pragma unroll
            for (int jj = 0; jj < 8; jj++)
                *(float4*)&ts[buf ^ 1][w + 4 * jj][lane * 4] = pre[jj];
        }
        __syncthreads();
        buf ^= 1;
    }

    // ======================= phase 2: partial softmax =======================
    {
        int r = w;
        float sv[NCHUNK];
        float m = -INFINITY;
#pragma unroll
        for (int i = 0; i < 8; i++) {
            sv[i] = sc[lane + 32 * i][r];
            m = fmaxf(m, sv[i]);
        }
#pragma unroll
        for (int off = 16; off > 0; off >>= 1)
            m = fmaxf(m, __shfl_xor_sync(0xffffffffu, m, off));
        float lsum = 0.f;
#pragma unroll
        for (int i = 0; i < 8; i++) {
            float p = (m == -INFINITY) ? 0.f : __expf(sv[i] - m);
            sc[lane + 32 * i][r] = p;
            lsum += p;
        }
#pragma unroll
        for (int off = 16; off > 0; off >>= 1)
            lsum += __shfl_xor_sync(0xffffffffu, lsum, off);
        if (lane == 0) {
            size_t mlidx = ((((size_t)b * NKV + h) * NREP + r) * NCHUNK + c) * 2;
            g_ml[mlidx]     = m;
            g_ml[mlidx + 1] = lsum;
        }
    }
    __syncthreads();

    // ======================= phase 3: P @ V (V stream) ======================
    // warp w accumulates rep w over ALL 256 rows; lane owns d-quad lane*4.
    float4 acc = make_float4(0.f, 0.f, 0.f, 0.f);

    // prefetch V tile 0
#pragma unroll
    for (int jj = 0; jj < 8; jj++) {
        int tpos = tbase + w + 4 * jj;
        float4 val = make_float4(0.f, 0.f, 0.f, 0.f);
        if (tpos < t_total) {
            const float* vrow = (tpos == start_pos)
                ? &g_v[(size_t)b * 1024 + h * HD]
                : &cache_v[(((size_t)b * MAXSEQ + tpos) * NKV + h) * HD];
            val = *(const float4*)(vrow + lane * 4);
        }
        pre[jj] = val;
    }
#pragma unroll
    for (int jj = 0; jj < 8; jj++)
        *(float4*)&ts[0][w + 4 * jj][lane * 4] = pre[jj];
    __syncthreads();

    buf = 0;
    for (int tile = 0; tile < 8; tile++) {
        if (tile < 7) {
            int trow0 = tbase + (tile + 1) * 32;
#pragma unroll
            for (int jj = 0; jj < 8; jj++) {
                int tpos = trow0 + w + 4 * jj;
                float4 val = make_float4(0.f, 0.f, 0.f, 0.f);
                if (tpos < t_total) {
                    const float* vrow = (tpos == start_pos)
                        ? &g_v[(size_t)b * 1024 + h * HD]
                        : &cache_v[(((size_t)b * MAXSEQ + tpos) * NKV + h) * HD];
                    val = *(const float4*)(vrow + lane * 4);
                }
                pre[jj] = val;
            }
        }
        // accumulate 32 rows of current tile
#pragma unroll 8
        for (int row = 0; row < 32; row++) {
            float p = sc[tile * 32 + row][w];
            float4 v4 = *(const float4*)&ts[buf][row][lane * 4];
            acc.x += p * v4.x; acc.y += p * v4.y;
            acc.z += p * v4.z; acc.w += p * v4.w;
        }
        if (tile < 7) {
#pragma unroll
            for (int jj = 0; jj < 8; jj++)
                *(float4*)&ts[buf ^ 1][w + 4 * jj][lane * 4] = pre[jj];
        }
        __syncthreads();
        buf ^= 1;
    }

    // write partial output: warp w -> rep w, lane -> d-quad
    *(float4*)&g_pout[(((((size_t)b * NKV + h) * NREP + w) * NCHUNK) + c) * HD +
                      lane * 4] = acc;
}

// ------------------------- combine partial softmax --------------------------
__global__ __launch_bounds__(128) void combine_kernel()
{
    int blk = blockIdx.x;                 // r + 4*(h + 8*b)
    int r = blk & 3;
    int h = (blk >> 2) & 7;
    int b = blk >> 5;
    int d = threadIdx.x;

    size_t base = (((size_t)b * NKV + h) * NREP + r) * NCHUNK;

    float mm[NCHUNK], ll[NCHUNK];
    float mg = -INFINITY;
#pragma unroll
    for (int c = 0; c < NCHUNK; c++) {
        mm[c] = g_ml[(base + c) * 2];
        ll[c] = g_ml[(base + c) * 2 + 1];
        if (ll[c] > 0.f) mg = fmaxf(mg, mm[c]);
    }
    float L = 0.f, o = 0.f;
#pragma unroll
    for (int c = 0; c < NCHUNK; c++) {
        if (ll[c] > 0.f) {
            float f = __expf(mm[c] - mg);
            L += ll[c] * f;
            o += f * g_pout[(base + c) * HD + d];
        }
    }
    g_attn[(size_t)b * DIM + (h * NREP + r) * HD + d] = o / L;
}

// ------------------------- O-proj split-K reduce ----------------------------
__global__ void o_finish(float* __restrict__ out)
{
    int i = blockIdx.x * blockDim.x + threadIdx.x;  // 32768 float4 elems
    if (i >= NB * DIM / 4) return;
    float4 s = make_float4(0.f, 0.f, 0.f, 0.f);
#pragma unroll
    for (int p = 0; p < O_SPLIT; p++) {
        float4 v = *((const float4*)&g_part[(size_t)p * NB * DIM] + i);
        s.x += v.x; s.y += v.y; s.z += v.z; s.w += v.w;
    }
    ((float4*)out)[i] = s;
}

// ------------------------- launcher -----------------------------------------
extern "C" void kernel_launch(void* const* d_in, const int* in_sizes, int n_in,
                              void* d_out, int out_size)
{
    const float* x  = (const float*)d_in[0];
    const float* fc = (const float*)d_in[1];
    const float* fs = (const float*)d_in[2];
    const float* wq = (const float*)d_in[3];
    const float* wk = (const float*)d_in[4];
    const float* wv = (const float*)d_in[5];
    const float* wo = (const float*)d_in[6];
    const float* ck = (const float*)d_in[7];
    const float* cv = (const float*)d_in[8];
    const int*   sp = (const int*)d_in[9];
    float* out = (float*)d_out;

    // QKV projection: 6144 cols, split-K=4 -> 96*4 = 384 blocks
    proj_kernel<<<96 * QKV_SPLIT, 128>>>(x, wq, wk, wv, 96, 4096, 5120,
                                         4096 / QKV_SPLIT, 6144);
    qkv_finish<<<384, 256>>>(fc, fs);
    // attention partials: 32*8*8 = 2048 blocks
    attn_kernel<<<2048, 128>>>(ck, cv, sp);
    combine_kernel<<<1024, 128>>>();
    // O projection: 4096 cols, split-K=8 -> 64*8 = 512 blocks
    proj_kernel<<<64 * O_SPLIT, 128>>>(nullptr, wo, wo, wo, 64, 4096, 8192,
                                       4096 / O_SPLIT, 4096);
    o_finish<<<128, 256>>>(out);
}

// round 5
// speedup vs baseline: 1.4806x; 1.0773x over previous
#include <cuda_runtime.h>
#include <cuda_bf16.h>
#include <math.h>

#define NB 32
#define DIM 4096
#define NKV 8
#define NREP 4
#define HD 128
#define MAXSEQ 2048
#define NCHUNK 8
#define CHUNK 256
#define QKV_SPLIT 16
#define O_SPLIT 16

// ------------------------- device scratch (no allocs allowed) ---------------
__device__ float g_q[NB * DIM];                          // rope'd Q
__device__ float g_k[NB * NKV * HD];                     // rope'd new K row
__device__ float g_v[NB * NKV * HD];                     // new V row
__device__ float g_attn[NB * DIM];                       // attention output
__device__ float g_part[QKV_SPLIT * NB * 6144];          // split-K partials
__device__ float g_pout[NB * NKV * NREP * NCHUNK * HD];  // attn partial outs
__device__ float g_ml[NB * NKV * NREP * NCHUNK * 2];     // (m, l) per chunk

// ------------------------- bf16x3 MMA projection GEMM -----------------------
// out_part[split][b][j] = sum_{k in split} A[b][k] * W[j][k]
// Block: 128 threads (4 warps). Block tile: M=32, N=128. Warp: M=32 x N=32.
// K-chunk = 64 (4 k16 steps). mma.sync.m16n8k16 bf16, 3 passes
// (hi*hi + lo*hi + hi*lo) for ~fp32 accuracy.

#define MMA_B16(acc, A0, A1, A2, A3, B0, B1)                                   \
    asm volatile(                                                              \
        "mma.sync.aligned.m16n8k16.row.col.f32.bf16.bf16.f32 "                 \
        "{%0,%1,%2,%3}, {%4,%5,%6,%7}, {%8,%9}, {%0,%1,%2,%3};"                \
        : "+f"(acc[0]), "+f"(acc[1]), "+f"(acc[2]), "+f"(acc[3])               \
        : "r"(A0), "r"(A1), "r"(A2), "r"(A3), "r"(B0), "r"(B1))

__device__ __forceinline__ void bf16_split(float v, unsigned& hbits, unsigned& lbits)
{
    __nv_bfloat16 h = __float2bfloat16_rn(v);
    float r = v - __bfloat162float(h);
    __nv_bfloat16 lo = __float2bfloat16_rn(r);
    hbits = (unsigned)__bfloat16_as_ushort(h);
    lbits = (unsigned)__bfloat16_as_ushort(lo);
}

__global__ __launch_bounds__(128) void proj_mma(
    const float* __restrict__ A,   // NB x 4096 (nullptr -> g_attn)
    const float* __restrict__ W0,
    const float* __restrict__ W1,
    const float* __restrict__ W2,
    int njb, int r1, int r2, int klen, int totalj)
{
    __shared__ unsigned sB[16 * 4 * 144];   // 36 KB
    __shared__ unsigned sAh[2 * 4 * 132];   // 4.2 KB
    __shared__ unsigned sAl[2 * 4 * 132];   // 4.2 KB

    const float* Ap = A ? A : g_attn;

    int jb    = blockIdx.x % njb;
    int split = blockIdx.x / njb;
    int j0    = jb * 128;

    const float* W;
    int jw;
    if (j0 < r1)      { W = W0; jw = j0; }
    else if (j0 < r2) { W = W1; jw = j0 - r1; }
    else              { W = W2; jw = j0 - r2; }

    int tid = threadIdx.x;
    int w   = tid >> 5, l = tid & 31;

    float acc[2][4][4];
#pragma unroll
    for (int i = 0; i < 2; i++)
#pragma unroll
        for (int j = 0; j < 4; j++)
#pragma unroll
            for (int c = 0; c < 4; c++) acc[i][j][c] = 0.f;

    int k0 = split * klen;
    int ksw   = l >> 3;            // k16-step this lane's pair falls in
    int prw   = (l >> 2) & 1;      // b0/b1 selector
    int lq    = l & 3;

    for (int kc = k0; kc < k0 + klen; kc += 64) {
        __syncthreads();
        // ---- stage W tile: warp w handles block-rows [32w, 32w+32) --------
#pragma unroll 4
        for (int rr = 0; rr < 32; rr++) {
            int n = w * 32 + rr;
            float2 v = *(const float2*)(W + (size_t)(jw + n) * 4096 + kc + 2 * l);
            unsigned h0, l0, h1, l1;
            bf16_split(v.x, h0, l0);
            bf16_split(v.y, h1, l1);
            unsigned uh = (h1 << 16) | h0;
            unsigned ul = (l1 << 16) | l0;
            int nt = n >> 3;
            int lanep = ((n & 7) << 2) + lq;
            *(uint2*)&sB[((nt * 4 + ksw) * 144) + lanep * 4 + prw * 2] =
                make_uint2(uh, ul);
        }
        // ---- stage A tile: warp w handles rows [8w, 8w+8) -----------------
#pragma unroll
        for (int rr = 0; rr < 8; rr++) {
            int m = w * 8 + rr;
            float2 v = *(const float2*)(Ap + (size_t)m * 4096 + kc + 2 * l);
            unsigned h0, l0, h1, l1;
            bf16_split(v.x, h0, l0);
            bf16_split(v.y, h1, l1);
            unsigned uh = (h1 << 16) | h0;
            unsigned ul = (l1 << 16) | l0;
            int mt = m >> 4;
            int lanep = ((m & 7) << 2) + lq;
            int anum  = ((m >> 3) & 1) | (prw << 1);
            int idx = (mt * 4 + ksw) * 132 + lanep * 4 + anum;
            sAh[idx] = uh;
            sAl[idx] = ul;
        }
        __syncthreads();

        // ---- compute ------------------------------------------------------
#pragma unroll
        for (int ks = 0; ks < 4; ks++) {
            uint4 ah0 = *(const uint4*)&sAh[(ks) * 132 + l * 4];
            uint4 al0 = *(const uint4*)&sAl[(ks) * 132 + l * 4];
            uint4 ah1 = *(const uint4*)&sAh[(4 + ks) * 132 + l * 4];
            uint4 al1 = *(const uint4*)&sAl[(4 + ks) * 132 + l * 4];
#pragma unroll
            for (int ntl = 0; ntl < 4; ntl++) {
                uint4 bb = *(const uint4*)&sB[((w * 4 + ntl) * 4 + ks) * 144 + l * 4];
                MMA_B16(acc[0][ntl], ah0.x, ah0.y, ah0.z, ah0.w, bb.x, bb.z);
                MMA_B16(acc[1][ntl], ah1.x, ah1.y, ah1.z, ah1.w, bb.x, bb.z);
                MMA_B16(acc[0][ntl], al0.x, al0.y, al0.z, al0.w, bb.x, bb.z);
                MMA_B16(acc[1][ntl], al1.x, al1.y, al1.z, al1.w, bb.x, bb.z);
                MMA_B16(acc[0][ntl], ah0.x, ah0.y, ah0.z, ah0.w, bb.y, bb.w);
                MMA_B16(acc[1][ntl], ah1.x, ah1.y, ah1.z, ah1.w, bb.y, bb.w);
            }
        }
    }

    // ---- epilogue: write split partials ----------------------------------
    size_t pbase = (size_t)split * NB * totalj;
#pragma unroll
    for (int mt = 0; mt < 2; mt++)
#pragma unroll
        for (int ntl = 0; ntl < 4; ntl++) {
            int m = mt * 16 + (l >> 2);
            int j = j0 + ((w * 4 + ntl) << 3) + (lq << 1);
            *(float2*)&g_part[pbase + (size_t)m * totalj + j] =
                make_float2(acc[mt][ntl][0], acc[mt][ntl][1]);
            *(float2*)&g_part[pbase + (size_t)(m + 8) * totalj + j] =
                make_float2(acc[mt][ntl][2], acc[mt][ntl][3]);
        }
}

// ------------------------- split-K reduce + RoPE ----------------------------
__global__ void qkv_finish(const float* __restrict__ fc, const float* __restrict__ fs)
{
    int p = blockIdx.x * blockDim.x + threadIdx.x;
    if (p >= NB * 3072) return;
    int b = p / 3072;
    int j = (p % 3072) * 2;

    float v0 = 0.f, v1 = 0.f;
#pragma unroll
    for (int s = 0; s < QKV_SPLIT; s++) {
        size_t base = (size_t)s * NB * 6144 + (size_t)b * 6144 + j;
        v0 += g_part[base];
        v1 += g_part[base + 1];
    }

    if (j < 5120) {
        int pi = (j & 127) >> 1;
        float c = fc[pi], s = fs[pi];
        float o0 = v0 * c - v1 * s;
        float o1 = v0 * s + v1 * c;
        if (j < 4096) {
            g_q[b * DIM + j]     = o0;
            g_q[b * DIM + j + 1] = o1;
        } else {
            g_k[b * 1024 + j - 4096]     = o0;
            g_k[b * 1024 + j - 4096 + 1] = o1;
        }
    } else {
        g_v[b * 1024 + j - 5120]     = v0;
        g_v[b * 1024 + j - 5120 + 1] = v1;
    }
}

// ------------------------- flash-decode attention ---------------------------
// One block per (b, kv_head, chunk). 128 threads = 4 warps.
// BOTH K and V streams smem-staged (MLP=8/thread) with double buffering.
__global__ __launch_bounds__(128) void attn_kernel(
    const float* __restrict__ cache_k, const float* __restrict__ cache_v,
    const int* __restrict__ sp)
{
    int blk = blockIdx.x;                 // c + 8*(h + 8*b)
    int c = blk & 7;
    int h = (blk >> 3) & 7;
    int b = blk >> 6;

    int tid = threadIdx.x;
    int w = tid >> 5, lane = tid & 31;

    int start_pos = *sp;
    int t_total = start_pos + 1;

    __shared__ float qs[4][HD];           // scaled q
    __shared__ float ts[2][32][132];      // staged K/V tiles
    __shared__ float sc[CHUNK][4];        // scores -> probs

    const float scale = 0.08838834764831845f;  // 1/sqrt(128)
    for (int i = tid; i < 4 * HD; i += 128) {
        int r = i >> 7, d = i & 127;
        qs[r][d] = g_q[(size_t)b * DIM + (h * NREP + r) * HD + d] * scale;
    }

    int tbase = c * CHUNK;
    float4 pre[8];

    // ======================= phase 1: scores (K stream) =====================
#pragma unroll
    for (int jj = 0; jj < 8; jj++) {
        int tpos = tbase + w + 4 * jj;
        float4 val = make_float4(0.f, 0.f, 0.f, 0.f);
        if (tpos < t_total) {
            const float* krow = (tpos == start_pos)
                ? &g_k[(size_t)b * 1024 + h * HD]
                : &cache_k[(((size_t)b * MAXSEQ + tpos) * NKV + h) * HD];
            val = *(const float4*)(krow + lane * 4);
        }
        pre[jj] = val;
    }
#pragma unroll
    for (int jj = 0; jj < 8; jj++)
        *(float4*)&ts[0][w + 4 * jj][lane * 4] = pre[jj];
    __syncthreads();

    int buf = 0;
    for (int tile = 0; tile < 8; tile++) {
        if (tile < 7) {
            int trow0 = tbase + (tile + 1) * 32;
#pragma unroll
            for (int jj = 0; jj < 8; jj++) {
                int tpos = trow0 + w + 4 * jj;
                float4 val = make_float4(0.f, 0.f, 0.f, 0.f);
                if (tpos < t_total) {
                    const float* krow = (tpos == start_pos)
                        ? &g_k[(size_t)b * 1024 + h * HD]
                        : &cache_k[(((size_t)b * MAXSEQ + tpos) * NKV + h) * HD];
                    val = *(const float4*)(krow + lane * 4);
                }
                pre[jj] = val;
            }
        }
        {
            int tpos = tbase + tile * 32 + lane;
            float s = 0.f;
#pragma unroll 8
            for (int dq = 0; dq < 32; dq++) {
                float4 k4 = *(const float4*)&ts[buf][lane][dq * 4];
                float4 q4 = *(const float4*)&qs[w][dq * 4];
                s += k4.x * q4.x + k4.y * q4.y + k4.z * q4.z + k4.w * q4.w;
            }
            sc[tile * 32 + lane][w] = (tpos < t_total) ? s : -INFINITY;
        }
        if (tile < 7) {
#pragma unroll
            for (int jj = 0; jj < 8; jj++)
                *(float4*)&ts[buf ^ 1][w + 4 * jj][lane * 4] = pre[jj];
        }
        __syncthreads();
        buf ^= 1;
    }

    // ======================= phase 2: partial softmax =======================
    {
        int r = w;
        float sv[NCHUNK];
        float m = -INFINITY;
#pragma unroll
        for (int i = 0; i < 8; i++) {
            sv[i] = sc[lane + 32 * i][r];
            m = fmaxf(m, sv[i]);
        }
#pragma unroll
        for (int off = 16; off > 0; off >>= 1)
            m = fmaxf(m, __shfl_xor_sync(0xffffffffu, m, off));
        float lsum = 0.f;
#pragma unroll
        for (int i = 0; i < 8; i++) {
            float p = (m == -INFINITY) ? 0.f : __expf(sv[i] - m);
            sc[lane + 32 * i][r] = p;
            lsum += p;
        }
#pragma unroll
        for (int off = 16; off > 0; off >>= 1)
            lsum += __shfl_xor_sync(0xffffffffu, lsum, off);
        if (lane == 0) {
            size_t mlidx = ((((size_t)b * NKV + h) * NREP + r) * NCHUNK + c) * 2;
            g_ml[mlidx]     = m;
            g_ml[mlidx + 1] = lsum;
        }
    }
    __syncthreads();

    // ======================= phase 3: P @ V (V stream) ======================
    float4 acc = make_float4(0.f, 0.f, 0.f, 0.f);

#pragma unroll
    for (int jj = 0; jj < 8; jj++) {
        int tpos = tbase + w + 4 * jj;
        float4 val = make_float4(0.f, 0.f, 0.f, 0.f);
        if (tpos < t_total) {
            const float* vrow = (tpos == start_pos)
                ? &g_v[(size_t)b * 1024 + h * HD]
                : &cache_v[(((size_t)b * MAXSEQ + tpos) * NKV + h) * HD];
            val = *(const float4*)(vrow + lane * 4);
        }
        pre[jj] = val;
    }
#pragma unroll
    for (int jj = 0; jj < 8; jj++)
        *(float4*)&ts[0][w + 4 * jj][lane * 4] = pre[jj];
    __syncthreads();

    buf = 0;
    for (int tile = 0; tile < 8; tile++) {
        if (tile < 7) {
            int trow0 = tbase + (tile + 1) * 32;
#pragma unroll
            for (int jj = 0; jj < 8; jj++) {
                int tpos = trow0 + w + 4 * jj;
                float4 val = make_float4(0.f, 0.f, 0.f, 0.f);
                if (tpos < t_total) {
                    const float* vrow = (tpos == start_pos)
                        ? &g_v[(size_t)b * 1024 + h * HD]
                        : &cache_v[(((size_t)b * MAXSEQ + tpos) * NKV + h) * HD];
                    val = *(const float4*)(vrow + lane * 4);
                }
                pre[jj] = val;
            }
        }
#pragma unroll 8
        for (int row = 0; row < 32; row++) {
            float p = sc[tile * 32 + row][w];
            float4 v4 = *(const float4*)&ts[buf][row][lane * 4];
            acc.x += p * v4.x; acc.y += p * v4.y;
            acc.z += p * v4.z; acc.w += p * v4.w;
        }
        if (tile < 7) {
#pragma unroll
            for (int jj = 0; jj < 8; jj++)
                *(float4*)&ts[buf ^ 1][w + 4 * jj][lane * 4] = pre[jj];
        }
        __syncthreads();
        buf ^= 1;
    }

    *(float4*)&g_pout[(((((size_t)b * NKV + h) * NREP + w) * NCHUNK) + c) * HD +
                      lane * 4] = acc;
}

// ------------------------- combine partial softmax --------------------------
__global__ __launch_bounds__(128) void combine_kernel()
{
    int blk = blockIdx.x;                 // r + 4*(h + 8*b)
    int r = blk & 3;
    int h = (blk >> 2) & 7;
    int b = blk >> 5;
    int d = threadIdx.x;

    size_t base = (((size_t)b * NKV + h) * NREP + r) * NCHUNK;

    float mm[NCHUNK], ll[NCHUNK];
    float mg = -INFINITY;
#pragma unroll
    for (int c = 0; c < NCHUNK; c++) {
        mm[c] = g_ml[(base + c) * 2];
        ll[c] = g_ml[(base + c) * 2 + 1];
        if (ll[c] > 0.f) mg = fmaxf(mg, mm[c]);
    }
    float L = 0.f, o = 0.f;
#pragma unroll
    for (int c = 0; c < NCHUNK; c++) {
        if (ll[c] > 0.f) {
            float f = __expf(mm[c] - mg);
            L += ll[c] * f;
            o += f * g_pout[(base + c) * HD + d];
        }
    }
    g_attn[(size_t)b * DIM + (h * NREP + r) * HD + d] = o / L;
}

// ------------------------- O-proj split-K reduce ----------------------------
__global__ void o_finish(float* __restrict__ out)
{
    int i = blockIdx.x * blockDim.x + threadIdx.x;  // 32768 float4 elems
    if (i >= NB * DIM / 4) return;
    float4 s = make_float4(0.f, 0.f, 0.f, 0.f);
#pragma unroll
    for (int p = 0; p < O_SPLIT; p++) {
        float4 v = *((const float4*)&g_part[(size_t)p * NB * DIM] + i);
        s.x += v.x; s.y += v.y; s.z += v.z; s.w += v.w;
    }
    ((float4*)out)[i] = s;
}

// ------------------------- launcher -----------------------------------------
extern "C" void kernel_launch(void* const* d_in, const int* in_sizes, int n_in,
                              void* d_out, int out_size)
{
    const float* x  = (const float*)d_in[0];
    const float* fc = (const float*)d_in[1];
    const float* fs = (const float*)d_in[2];
    const float* wq = (const float*)d_in[3];
    const float* wk = (const float*)d_in[4];
    const float* wv = (const float*)d_in[5];
    const float* wo = (const float*)d_in[6];
    const float* ck = (const float*)d_in[7];
    const float* cv = (const float*)d_in[8];
    const int*   sp = (const int*)d_in[9];
    float* out = (float*)d_out;

    // QKV projection: 48 n-slabs x split 16 = 768 blocks, klen 256
    proj_mma<<<48 * QKV_SPLIT, 128>>>(x, wq, wk, wv, 48, 4096, 5120,
                                      4096 / QKV_SPLIT, 6144);
    qkv_finish<<<384, 256>>>(fc, fs);
    attn_kernel<<<2048, 128>>>(ck, cv, sp);
    combine_kernel<<<1024, 128>>>();
    // O projection: 32 n-slabs x split 16 = 512 blocks, klen 256
    proj_mma<<<32 * O_SPLIT, 128>>>(nullptr, wo, wo, wo, 32, 4096, 8192,
                                    4096 / O_SPLIT, 4096);
    o_finish<<<128, 256>>>(out);
}

// round 6
// speedup vs baseline: 1.5754x; 1.0641x over previous
#include <cuda_runtime.h>
#include <cuda_bf16.h>
#include <math.h>

#define NB 32
#define DIM 4096
#define NKV 8
#define NREP 4
#define HD 128
#define MAXSEQ 2048
#define NCHUNK 8
#define CHUNK 256
#define QKV_SPLIT 16
#define O_SPLIT 16

// ------------------------- device scratch (no allocs allowed) ---------------
__device__ float g_q[NB * DIM];                          // rope'd Q
__device__ float g_k[NB * NKV * HD];                     // rope'd new K row
__device__ float g_v[NB * NKV * HD];                     // new V row
__device__ float g_attn[NB * DIM];                       // attention output
__device__ float g_part[QKV_SPLIT * NB * 6144];          // split-K partials
__device__ float g_pout[NB * NKV * NREP * NCHUNK * HD];  // attn partial outs
__device__ float g_ml[NB * NKV * NREP * NCHUNK * 2];     // (m, l) per chunk

// ------------------------- bf16x3 MMA projection GEMM -----------------------
#define MMA_B16(acc, A0, A1, A2, A3, B0, B1)                                   \
    asm volatile(                                                              \
        "mma.sync.aligned.m16n8k16.row.col.f32.bf16.bf16.f32 "                 \
        "{%0,%1,%2,%3}, {%4,%5,%6,%7}, {%8,%9}, {%0,%1,%2,%3};"                \
        : "+f"(acc[0]), "+f"(acc[1]), "+f"(acc[2]), "+f"(acc[3])               \
        : "r"(A0), "r"(A1), "r"(A2), "r"(A3), "r"(B0), "r"(B1))

__device__ __forceinline__ void bf16_split(float v, unsigned& hbits, unsigned& lbits)
{
    __nv_bfloat16 h = __float2bfloat16_rn(v);
    float r = v - __bfloat162float(h);
    __nv_bfloat16 lo = __float2bfloat16_rn(r);
    hbits = (unsigned)__bfloat16_as_ushort(h);
    lbits = (unsigned)__bfloat16_as_ushort(lo);
}

__global__ __launch_bounds__(128) void proj_mma(
    const float* __restrict__ A,   // NB x 4096 (nullptr -> g_attn)
    const float* __restrict__ W0,
    const float* __restrict__ W1,
    const float* __restrict__ W2,
    int njb, int r1, int r2, int klen, int totalj)
{
    __shared__ unsigned sB[16 * 4 * 144];   // 36 KB
    __shared__ unsigned sAh[2 * 4 * 132];   // 4.2 KB
    __shared__ unsigned sAl[2 * 4 * 132];   // 4.2 KB

    const float* Ap = A ? A : g_attn;

    int jb    = blockIdx.x % njb;
    int split = blockIdx.x / njb;
    int j0    = jb * 128;

    const float* W;
    int jw;
    if (j0 < r1)      { W = W0; jw = j0; }
    else if (j0 < r2) { W = W1; jw = j0 - r1; }
    else              { W = W2; jw = j0 - r2; }

    int tid = threadIdx.x;
    int w   = tid >> 5, l = tid & 31;

    float acc[2][4][4];
#pragma unroll
    for (int i = 0; i < 2; i++)
#pragma unroll
        for (int j = 0; j < 4; j++)
#pragma unroll
            for (int c = 0; c < 4; c++) acc[i][j][c] = 0.f;

    int k0 = split * klen;
    int ksw   = l >> 3;
    int prw   = (l >> 2) & 1;
    int lq    = l & 3;

    for (int kc = k0; kc < k0 + klen; kc += 64) {
        __syncthreads();
#pragma unroll 4
        for (int rr = 0; rr < 32; rr++) {
            int n = w * 32 + rr;
            float2 v = *(const float2*)(W + (size_t)(jw + n) * 4096 + kc + 2 * l);
            unsigned h0, l0, h1, l1;
            bf16_split(v.x, h0, l0);
            bf16_split(v.y, h1, l1);
            unsigned uh = (h1 << 16) | h0;
            unsigned ul = (l1 << 16) | l0;
            int nt = n >> 3;
            int lanep = ((n & 7) << 2) + lq;
            *(uint2*)&sB[((nt * 4 + ksw) * 144) + lanep * 4 + prw * 2] =
                make_uint2(uh, ul);
        }
#pragma unroll
        for (int rr = 0; rr < 8; rr++) {
            int m = w * 8 + rr;
            float2 v = *(const float2*)(Ap + (size_t)m * 4096 + kc + 2 * l);
            unsigned h0, l0, h1, l1;
            bf16_split(v.x, h0, l0);
            bf16_split(v.y, h1, l1);
            unsigned uh = (h1 << 16) | h0;
            unsigned ul = (l1 << 16) | l0;
            int mt = m >> 4;
            int lanep = ((m & 7) << 2) + lq;
            int anum  = ((m >> 3) & 1) | (prw << 1);
            int idx = (mt * 4 + ksw) * 132 + lanep * 4 + anum;
            sAh[idx] = uh;
            sAl[idx] = ul;
        }
        __syncthreads();

#pragma unroll
        for (int ks = 0; ks < 4; ks++) {
            uint4 ah0 = *(const uint4*)&sAh[(ks) * 132 + l * 4];
            uint4 al0 = *(const uint4*)&sAl[(ks) * 132 + l * 4];
            uint4 ah1 = *(const uint4*)&sAh[(4 + ks) * 132 + l * 4];
            uint4 al1 = *(const uint4*)&sAl[(4 + ks) * 132 + l * 4];
#pragma unroll
            for (int ntl = 0; ntl < 4; ntl++) {
                uint4 bb = *(const uint4*)&sB[((w * 4 + ntl) * 4 + ks) * 144 + l * 4];
                MMA_B16(acc[0][ntl], ah0.x, ah0.y, ah0.z, ah0.w, bb.x, bb.z);
                MMA_B16(acc[1][ntl], ah1.x, ah1.y, ah1.z, ah1.w, bb.x, bb.z);
                MMA_B16(acc[0][ntl], al0.x, al0.y, al0.z, al0.w, bb.x, bb.z);
                MMA_B16(acc[1][ntl], al1.x, al1.y, al1.z, al1.w, bb.x, bb.z);
                MMA_B16(acc[0][ntl], ah0.x, ah0.y, ah0.z, ah0.w, bb.y, bb.w);
                MMA_B16(acc[1][ntl], ah1.x, ah1.y, ah1.z, ah1.w, bb.y, bb.w);
            }
        }
    }

    size_t pbase = (size_t)split * NB * totalj;
#pragma unroll
    for (int mt = 0; mt < 2; mt++)
#pragma unroll
        for (int ntl = 0; ntl < 4; ntl++) {
            int m = mt * 16 + (l >> 2);
            int j = j0 + ((w * 4 + ntl) << 3) + (lq << 1);
            *(float2*)&g_part[pbase + (size_t)m * totalj + j] =
                make_float2(acc[mt][ntl][0], acc[mt][ntl][1]);
            *(float2*)&g_part[pbase + (size_t)(m + 8) * totalj + j] =
                make_float2(acc[mt][ntl][2], acc[mt][ntl][3]);
        }
}

// ------------------------- split-K reduce + RoPE ----------------------------
__global__ void qkv_finish(const float* __restrict__ fc, const float* __restrict__ fs)
{
    int p = blockIdx.x * blockDim.x + threadIdx.x;
    if (p >= NB * 3072) return;
    int b = p / 3072;
    int j = (p % 3072) * 2;

    float v0 = 0.f, v1 = 0.f;
#pragma unroll
    for (int s = 0; s < QKV_SPLIT; s++) {
        size_t base = (size_t)s * NB * 6144 + (size_t)b * 6144 + j;
        v0 += g_part[base];
        v1 += g_part[base + 1];
    }

    if (j < 5120) {
        int pi = (j & 127) >> 1;
        float c = fc[pi], s = fs[pi];
        float o0 = v0 * c - v1 * s;
        float o1 = v0 * s + v1 * c;
        if (j < 4096) {
            g_q[b * DIM + j]     = o0;
            g_q[b * DIM + j + 1] = o1;
        } else {
            g_k[b * 1024 + j - 4096]     = o0;
            g_k[b * 1024 + j - 4096 + 1] = o1;
        }
    } else {
        g_v[b * 1024 + j - 5120]     = v0;
        g_v[b * 1024 + j - 5120 + 1] = v1;
    }
}

// ------------------------- flash-decode attention ---------------------------
// One block per (b, kv_head, chunk). 128 threads = 4 warps.
// K/V tiles staged once per CTA (MLP=8, double-buffered). Rows partitioned
// across warps so each tile is read from smem exactly once.
// Tile row stride = 144 floats -> conflict-free for both access patterns.
__global__ __launch_bounds__(128) void attn_kernel(
    const float* __restrict__ cache_k, const float* __restrict__ cache_v,
    const int* __restrict__ sp)
{
    int blk = blockIdx.x;                 // c + 8*(h + 8*b)
    int c = blk & 7;
    int h = (blk >> 3) & 7;
    int b = blk >> 6;

    int tid = threadIdx.x;
    int w = tid >> 5, lane = tid & 31;

    int start_pos = *sp;
    int t_total = start_pos + 1;

    __shared__ float qs[4][HD];           // scaled q, 2KB
    __shared__ float ts[2][32][144];      // staged K/V tiles, 36.9KB
    __shared__ float sc[CHUNK][4];        // scores -> probs, 4KB
    __shared__ float red[4][4][HD];       // warp x rep x d, 8KB

    const float scale = 0.08838834764831845f;  // 1/sqrt(128)
    for (int i = tid; i < 4 * HD; i += 128) {
        int r = i >> 7, d = i & 127;
        qs[r][d] = g_q[(size_t)b * DIM + (h * NREP + r) * HD + d] * scale;
    }

    int tbase = c * CHUNK;
    float4 pre[8];

    int myrow  = w * 8 + (lane >> 2);     // phase-1 row within tile
    int dgrp   = lane & 3;                // phase-1 dim group

    // ======================= phase 1: scores (K stream) =====================
#pragma unroll
    for (int jj = 0; jj < 8; jj++) {
        int tpos = tbase + w + 4 * jj;
        float4 val = make_float4(0.f, 0.f, 0.f, 0.f);
        if (tpos < t_total) {
            const float* krow = (tpos == start_pos)
                ? &g_k[(size_t)b * 1024 + h * HD]
                : &cache_k[(((size_t)b * MAXSEQ + tpos) * NKV + h) * HD];
            val = *(const float4*)(krow + lane * 4);
        }
        pre[jj] = val;
    }
#pragma unroll
    for (int jj = 0; jj < 8; jj++)
        *(float4*)&ts[0][w + 4 * jj][lane * 4] = pre[jj];
    __syncthreads();

    int buf = 0;
    for (int tile = 0; tile < 8; tile++) {
        if (tile < 7) {
            int trow0 = tbase + (tile + 1) * 32;
#pragma unroll
            for (int jj = 0; jj < 8; jj++) {
                int tpos = trow0 + w + 4 * jj;
                float4 val = make_float4(0.f, 0.f, 0.f, 0.f);
                if (tpos < t_total) {
                    const float* krow = (tpos == start_pos)
                        ? &g_k[(size_t)b * 1024 + h * HD]
                        : &cache_k[(((size_t)b * MAXSEQ + tpos) * NKV + h) * HD];
                    val = *(const float4*)(krow + lane * 4);
                }
                pre[jj] = val;
            }
        }
        // compute: 8 rows/warp, 4 lanes/row, each lane all 4 reps over 32 dims
        {
            float s0 = 0.f, s1 = 0.f, s2 = 0.f, s3 = 0.f;
#pragma unroll
            for (int qq = 0; qq < 8; qq++) {
                int quad = dgrp + 4 * qq;
                float4 k4 = *(const float4*)&ts[buf][myrow][quad * 4];
                float4 q0 = *(const float4*)&qs[0][quad * 4];
                float4 q1 = *(const float4*)&qs[1][quad * 4];
                float4 q2 = *(const float4*)&qs[2][quad * 4];
                float4 q3 = *(const float4*)&qs[3][quad * 4];
                s0 += k4.x * q0.x + k4.y * q0.y + k4.z * q0.z + k4.w * q0.w;
                s1 += k4.x * q1.x + k4.y * q1.y + k4.z * q1.z + k4.w * q1.w;
                s2 += k4.x * q2.x + k4.y * q2.y + k4.z * q2.z + k4.w * q2.w;
                s3 += k4.x * q3.x + k4.y * q3.y + k4.z * q3.z + k4.w * q3.w;
            }
            // reduce across the 4 lanes sharing this row
#pragma unroll
            for (int off = 1; off < 4; off <<= 1) {
                s0 += __shfl_xor_sync(0xffffffffu, s0, off);
                s1 += __shfl_xor_sync(0xffffffffu, s1, off);
                s2 += __shfl_xor_sync(0xffffffffu, s2, off);
                s3 += __shfl_xor_sync(0xffffffffu, s3, off);
            }
            if (dgrp == 0) {
                int tl = tile * 32 + myrow;
                bool valid = (tbase + tl) < t_total;
                *(float4*)&sc[tl][0] = valid
                    ? make_float4(s0, s1, s2, s3)
                    : make_float4(-INFINITY, -INFINITY, -INFINITY, -INFINITY);
            }
        }
        if (tile < 7) {
#pragma unroll
            for (int jj = 0; jj < 8; jj++)
                *(float4*)&ts[buf ^ 1][w + 4 * jj][lane * 4] = pre[jj];
        }
        __syncthreads();
        buf ^= 1;
    }

    // ======================= phase 2: partial softmax =======================
    {
        int r = w;
        float sv[NCHUNK];
        float m = -INFINITY;
#pragma unroll
        for (int i = 0; i < 8; i++) {
            sv[i] = sc[lane + 32 * i][r];
            m = fmaxf(m, sv[i]);
        }
#pragma unroll
        for (int off = 16; off > 0; off >>= 1)
            m = fmaxf(m, __shfl_xor_sync(0xffffffffu, m, off));
        float lsum = 0.f;
#pragma unroll
        for (int i = 0; i < 8; i++) {
            float p = (m == -INFINITY) ? 0.f : __expf(sv[i] - m);
            sc[lane + 32 * i][r] = p;
            lsum += p;
        }
#pragma unroll
        for (int off = 16; off > 0; off >>= 1)
            lsum += __shfl_xor_sync(0xffffffffu, lsum, off);
        if (lane == 0) {
            size_t mlidx = ((((size_t)b * NKV + h) * NREP + r) * NCHUNK + c) * 2;
            g_ml[mlidx]     = m;
            g_ml[mlidx + 1] = lsum;
        }
    }
    __syncthreads();

    // ======================= phase 3: P @ V (V stream) ======================
    // warp w handles rows [w*8, w*8+8) of each tile, all 4 reps; lane owns
    // d-quad lane. Cross-warp reduction via red[] at the end.
    float4 acc0 = make_float4(0.f, 0.f, 0.f, 0.f);
    float4 acc1 = acc0, acc2 = acc0, acc3 = acc0;

#pragma unroll
    for (int jj = 0; jj < 8; jj++) {
        int tpos = tbase + w + 4 * jj;
        float4 val = make_float4(0.f, 0.f, 0.f, 0.f);
        if (tpos < t_total) {
            const float* vrow = (tpos == start_pos)
                ? &g_v[(size_t)b * 1024 + h * HD]
                : &cache_v[(((size_t)b * MAXSEQ + tpos) * NKV + h) * HD];
            val = *(const float4*)(vrow + lane * 4);
        }
        pre[jj] = val;
    }
#pragma unroll
    for (int jj = 0; jj < 8; jj++)
        *(float4*)&ts[0][w + 4 * jj][lane * 4] = pre[jj];
    __syncthreads();

    buf = 0;
    for (int tile = 0; tile < 8; tile++) {
        if (tile < 7) {
            int trow0 = tbase + (tile + 1) * 32;
#pragma unroll
            for (int jj = 0; jj < 8; jj++) {
                int tpos = trow0 + w + 4 * jj;
                float4 val = make_float4(0.f, 0.f, 0.f, 0.f);
                if (tpos < t_total) {
                    const float* vrow = (tpos == start_pos)
                        ? &g_v[(size_t)b * 1024 + h * HD]
                        : &cache_v[(((size_t)b * MAXSEQ + tpos) * NKV + h) * HD];
                    val = *(const float4*)(vrow + lane * 4);
                }
                pre[jj] = val;
            }
        }
#pragma unroll
        for (int rr = 0; rr < 8; rr++) {
            int row = w * 8 + rr;
            float4 p  = *(const float4*)&sc[tile * 32 + row][0];
            float4 v4 = *(const float4*)&ts[buf][row][lane * 4];
            acc0.x += p.x * v4.x; acc0.y += p.x * v4.y; acc0.z += p.x * v4.z; acc0.w += p.x * v4.w;
            acc1.x += p.y * v4.x; acc1.y += p.y * v4.y; acc1.z += p.y * v4.z; acc1.w += p.y * v4.w;
            acc2.x += p.z * v4.x; acc2.y += p.z * v4.y; acc2.z += p.z * v4.z; acc2.w += p.z * v4.w;
            acc3.x += p.w * v4.x; acc3.y += p.w * v4.y; acc3.z += p.w * v4.z; acc3.w += p.w * v4.w;
        }
        if (tile < 7) {
#pragma unroll
            for (int jj = 0; jj < 8; jj++)
                *(float4*)&ts[buf ^ 1][w + 4 * jj][lane * 4] = pre[jj];
        }
        __syncthreads();
        buf ^= 1;
    }

    *(float4*)&red[w][0][lane * 4] = acc0;
    *(float4*)&red[w][1][lane * 4] = acc1;
    *(float4*)&red[w][2][lane * 4] = acc2;
    *(float4*)&red[w][3][lane * 4] = acc3;
    __syncthreads();

    for (int i = tid; i < 4 * HD; i += 128) {
        int r = i >> 7, d = i & 127;
        float v = red[0][r][d] + red[1][r][d] + red[2][r][d] + red[3][r][d];
        g_pout[(((((size_t)b * NKV + h) * NREP + r) * NCHUNK) + c) * HD + d] = v;
    }
}

// ------------------------- combine partial softmax --------------------------
__global__ __launch_bounds__(128) void combine_kernel()
{
    int blk = blockIdx.x;                 // r + 4*(h + 8*b)
    int r = blk & 3;
    int h = (blk >> 2) & 7;
    int b = blk >> 5;
    int d = threadIdx.x;

    size_t base = (((size_t)b * NKV + h) * NREP + r) * NCHUNK;

    float mm[NCHUNK], ll[NCHUNK];
    float mg = -INFINITY;
#pragma unroll
    for (int c = 0; c < NCHUNK; c++) {
        mm[c] = g_ml[(base + c) * 2];
        ll[c] = g_ml[(base + c) * 2 + 1];
        if (ll[c] > 0.f) mg = fmaxf(mg, mm[c]);
    }
    float L = 0.f, o = 0.f;
#pragma unroll
    for (int c = 0; c < NCHUNK; c++) {
        if (ll[c] > 0.f) {
            float f = __expf(mm[c] - mg);
            L += ll[c] * f;
            o += f * g_pout[(base + c) * HD + d];
        }
    }
    g_attn[(size_t)b * DIM + (h * NREP + r) * HD + d] = o / L;
}

// ------------------------- O-proj split-K reduce ----------------------------
__global__ void o_finish(float* __restrict__ out)
{
    int i = blockIdx.x * blockDim.x + threadIdx.x;  // 32768 float4 elems
    if (i >= NB * DIM / 4) return;
    float4 s = make_float4(0.f, 0.f, 0.f, 0.f);
#pragma unroll
    for (int p = 0; p < O_SPLIT; p++) {
        float4 v = *((const float4*)&g_part[(size_t)p * NB * DIM] + i);
        s.x += v.x; s.y += v.y; s.z += v.z; s.w += v.w;
    }
    ((float4*)out)[i] = s;
}

// ------------------------- launcher -----------------------------------------
extern "C" void kernel_launch(void* const* d_in, const int* in_sizes, int n_in,
                              void* d_out, int out_size)
{
    const float* x  = (const float*)d_in[0];
    const float* fc = (const float*)d_in[1];
    const float* fs = (const float*)d_in[2];
    const float* wq = (const float*)d_in[3];
    const float* wk = (const float*)d_in[4];
    const float* wv = (const float*)d_in[5];
    const float* wo = (const float*)d_in[6];
    const float* ck = (const float*)d_in[7];
    const float* cv = (const float*)d_in[8];
    const int*   sp = (const int*)d_in[9];
    float* out = (float*)d_out;

    // QKV projection: 48 n-slabs x split 16 = 768 blocks
    proj_mma<<<48 * QKV_SPLIT, 128>>>(x, wq, wk, wv, 48, 4096, 5120,
                                      4096 / QKV_SPLIT, 6144);
    qkv_finish<<<384, 256>>>(fc, fs);
    attn_kernel<<<2048, 128>>>(ck, cv, sp);
    combine_kernel<<<1024, 128>>>();
    // O projection: 32 n-slabs x split 16 = 512 blocks
    proj_mma<<<32 * O_SPLIT, 128>>>(nullptr, wo, wo, wo, 32, 4096, 8192,
                                    4096 / O_SPLIT, 4096);
    o_finish<<<128, 256>>>(out);
}

// round 7
// speedup vs baseline: 1.7137x; 1.0878x over previous
#include <cuda_runtime.h>
#include <cuda_bf16.h>
#include <math.h>

#define NB 32
#define DIM 4096
#define NKV 8
#define NREP 4
#define HD 128
#define MAXSEQ 2048
#define NCHUNK 8
#define CHUNK 256
#define QKV_SPLIT 16
#define O_SPLIT 16

// ------------------------- device scratch (no allocs allowed) ---------------
__device__ float g_q[NB * DIM];                          // rope'd Q
__device__ float g_k[NB * NKV * HD];                     // rope'd new K row
__device__ float g_v[NB * NKV * HD];                     // new V row
__device__ float g_attn[NB * DIM];                       // attention output
__device__ float g_part[QKV_SPLIT * NB * 6144];          // split-K partials
__device__ float g_pout[NB * NKV * NREP * NCHUNK * HD];  // attn partial outs
__device__ float g_ml[NB * NKV * NREP * NCHUNK * 2];     // (m, l) per chunk

// ------------------------- bf16x3 MMA projection GEMM -----------------------
#define MMA_B16(acc, A0, A1, A2, A3, B0, B1)                                   \
    asm volatile(                                                              \
        "mma.sync.aligned.m16n8k16.row.col.f32.bf16.bf16.f32 "                 \
        "{%0,%1,%2,%3}, {%4,%5,%6,%7}, {%8,%9}, {%0,%1,%2,%3};"                \
        : "+f"(acc[0]), "+f"(acc[1]), "+f"(acc[2]), "+f"(acc[3])               \
        : "r"(A0), "r"(A1), "r"(A2), "r"(A3), "r"(B0), "r"(B1))

__device__ __forceinline__ void bf16_split(float v, unsigned& hbits, unsigned& lbits)
{
    __nv_bfloat16 h = __float2bfloat16_rn(v);
    float r = v - __bfloat162float(h);
    __nv_bfloat16 lo = __float2bfloat16_rn(r);
    hbits = (unsigned)__bfloat16_as_ushort(h);
    lbits = (unsigned)__bfloat16_as_ushort(lo);
}

__global__ __launch_bounds__(128) void proj_mma(
    const float* __restrict__ A,   // NB x 4096 (nullptr -> g_attn)
    const float* __restrict__ W0,
    const float* __restrict__ W1,
    const float* __restrict__ W2,
    int njb, int r1, int r2, int klen, int totalj)
{
    __shared__ unsigned sB[16 * 4 * 144];   // 36 KB
    __shared__ unsigned sAh[2 * 4 * 132];   // 4.2 KB
    __shared__ unsigned sAl[2 * 4 * 132];   // 4.2 KB

    const float* Ap = A ? A : g_attn;

    int jb    = blockIdx.x % njb;
    int split = blockIdx.x / njb;
    int j0    = jb * 128;

    const float* W;
    int jw;
    if (j0 < r1)      { W = W0; jw = j0; }
    else if (j0 < r2) { W = W1; jw = j0 - r1; }
    else              { W = W2; jw = j0 - r2; }

    int tid = threadIdx.x;
    int w   = tid >> 5, l = tid & 31;

    float acc[2][4][4];
#pragma unroll
    for (int i = 0; i < 2; i++)
#pragma unroll
        for (int j = 0; j < 4; j++)
#pragma unroll
            for (int c = 0; c < 4; c++) acc[i][j][c] = 0.f;

    int k0 = split * klen;
    int ksw   = l >> 3;
    int prw   = (l >> 2) & 1;
    int lq    = l & 3;

    for (int kc = k0; kc < k0 + klen; kc += 64) {
        __syncthreads();
#pragma unroll 4
        for (int rr = 0; rr < 32; rr++) {
            int n = w * 32 + rr;
            float2 v = *(const float2*)(W + (size_t)(jw + n) * 4096 + kc + 2 * l);
            unsigned h0, l0, h1, l1;
            bf16_split(v.x, h0, l0);
            bf16_split(v.y, h1, l1);
            unsigned uh = (h1 << 16) | h0;
            unsigned ul = (l1 << 16) | l0;
            int nt = n >> 3;
            int lanep = ((n & 7) << 2) + lq;
            *(uint2*)&sB[((nt * 4 + ksw) * 144) + lanep * 4 + prw * 2] =
                make_uint2(uh, ul);
        }
#pragma unroll
        for (int rr = 0; rr < 8; rr++) {
            int m = w * 8 + rr;
            float2 v = *(const float2*)(Ap + (size_t)m * 4096 + kc + 2 * l);
            unsigned h0, l0, h1, l1;
            bf16_split(v.x, h0, l0);
            bf16_split(v.y, h1, l1);
            unsigned uh = (h1 << 16) | h0;
            unsigned ul = (l1 << 16) | l0;
            int mt = m >> 4;
            int lanep = ((m & 7) << 2) + lq;
            int anum  = ((m >> 3) & 1) | (prw << 1);
            int idx = (mt * 4 + ksw) * 132 + lanep * 4 + anum;
            sAh[idx] = uh;
            sAl[idx] = ul;
        }
        __syncthreads();

#pragma unroll
        for (int ks = 0; ks < 4; ks++) {
            uint4 ah0 = *(const uint4*)&sAh[(ks) * 132 + l * 4];
            uint4 al0 = *(const uint4*)&sAl[(ks) * 132 + l * 4];
            uint4 ah1 = *(const uint4*)&sAh[(4 + ks) * 132 + l * 4];
            uint4 al1 = *(const uint4*)&sAl[(4 + ks) * 132 + l * 4];
#pragma unroll
            for (int ntl = 0; ntl < 4; ntl++) {
                uint4 bb = *(const uint4*)&sB[((w * 4 + ntl) * 4 + ks) * 144 + l * 4];
                MMA_B16(acc[0][ntl], ah0.x, ah0.y, ah0.z, ah0.w, bb.x, bb.z);
                MMA_B16(acc[1][ntl], ah1.x, ah1.y, ah1.z, ah1.w, bb.x, bb.z);
                MMA_B16(acc[0][ntl], al0.x, al0.y, al0.z, al0.w, bb.x, bb.z);
                MMA_B16(acc[1][ntl], al1.x, al1.y, al1.z, al1.w, bb.x, bb.z);
                MMA_B16(acc[0][ntl], ah0.x, ah0.y, ah0.z, ah0.w, bb.y, bb.w);
                MMA_B16(acc[1][ntl], ah1.x, ah1.y, ah1.z, ah1.w, bb.y, bb.w);
            }
        }
    }

    size_t pbase = (size_t)split * NB * totalj;
#pragma unroll
    for (int mt = 0; mt < 2; mt++)
#pragma unroll
        for (int ntl = 0; ntl < 4; ntl++) {
            int m = mt * 16 + (l >> 2);
            int j = j0 + ((w * 4 + ntl) << 3) + (lq << 1);
            *(float2*)&g_part[pbase + (size_t)m * totalj + j] =
                make_float2(acc[mt][ntl][0], acc[mt][ntl][1]);
            *(float2*)&g_part[pbase + (size_t)(m + 8) * totalj + j] =
                make_float2(acc[mt][ntl][2], acc[mt][ntl][3]);
        }
}

// ------------------------- split-K reduce + RoPE ----------------------------
__global__ void qkv_finish(const float* __restrict__ fc, const float* __restrict__ fs)
{
    int p = blockIdx.x * blockDim.x + threadIdx.x;
    if (p >= NB * 3072) return;
    int b = p / 3072;
    int j = (p % 3072) * 2;

    float v0 = 0.f, v1 = 0.f;
#pragma unroll
    for (int s = 0; s < QKV_SPLIT; s++) {
        size_t base = (size_t)s * NB * 6144 + (size_t)b * 6144 + j;
        v0 += g_part[base];
        v1 += g_part[base + 1];
    }

    if (j < 5120) {
        int pi = (j & 127) >> 1;
        float c = fc[pi], s = fs[pi];
        float o0 = v0 * c - v1 * s;
        float o1 = v0 * s + v1 * c;
        if (j < 4096) {
            g_q[b * DIM + j]     = o0;
            g_q[b * DIM + j + 1] = o1;
        } else {
            g_k[b * 1024 + j - 4096]     = o0;
            g_k[b * 1024 + j - 4096 + 1] = o1;
        }
    } else {
        g_v[b * 1024 + j - 5120]     = v0;
        g_v[b * 1024 + j - 5120 + 1] = v1;
    }
}

// ------------------------- flash-decode attention ---------------------------
// One block per (b, kv_head, chunk). 128 threads = 4 warps.
// Q held in REGISTERS (16 float4/lane: 4 reps x 4 quads). K/V tiles staged
// once per CTA (MLP=8, double-buffered); each tile read from smem once.
// Phase-1 lane map: lane = rowgrp*8 + e; lane owns dims quads e+8*qq.
__global__ __launch_bounds__(128, 4) void attn_kernel(
    const float* __restrict__ cache_k, const float* __restrict__ cache_v,
    const int* __restrict__ sp)
{
    int blk = blockIdx.x;                 // c + 8*(h + 8*b)
    int c = blk & 7;
    int h = (blk >> 3) & 7;
    int b = blk >> 6;

    int tid = threadIdx.x;
    int w = tid >> 5, lane = tid & 31;
    int rowgrp = lane >> 3;               // 0..3
    int e      = lane & 7;                // dim-eighth

    int start_pos = *sp;
    int t_total = start_pos + 1;

    __shared__ float ts[2][32][144];      // staged K/V tiles, 36.9KB
    __shared__ float sc[CHUNK][4];        // scores -> probs, 4KB
    __shared__ float red[4][4][HD];       // warp x rep x d, 8KB

    const float scale = 0.08838834764831845f;  // 1/sqrt(128)

    // Q in registers: qreg[rep][qq] = q[h*4+rep][ (e+8*qq)*4 .. +3 ] * scale
    float4 qreg[4][4];
#pragma unroll
    for (int r = 0; r < 4; r++)
#pragma unroll
        for (int qq = 0; qq < 4; qq++) {
            float4 v = *(const float4*)&g_q[(size_t)b * DIM + (h * NREP + r) * HD +
                                            (e + 8 * qq) * 4];
            qreg[r][qq] = make_float4(v.x * scale, v.y * scale,
                                      v.z * scale, v.w * scale);
        }

    int tbase = c * CHUNK;
    float4 pre[8];

    // ======================= phase 1: scores (K stream) =====================
#pragma unroll
    for (int jj = 0; jj < 8; jj++) {
        int tpos = tbase + w + 4 * jj;
        float4 val = make_float4(0.f, 0.f, 0.f, 0.f);
        if (tpos < t_total) {
            const float* krow = (tpos == start_pos)
                ? &g_k[(size_t)b * 1024 + h * HD]
                : &cache_k[(((size_t)b * MAXSEQ + tpos) * NKV + h) * HD];
            val = *(const float4*)(krow + lane * 4);
        }
        pre[jj] = val;
    }
#pragma unroll
    for (int jj = 0; jj < 8; jj++)
        *(float4*)&ts[0][w + 4 * jj][lane * 4] = pre[jj];
    __syncthreads();

    int buf = 0;
    for (int tile = 0; tile < 8; tile++) {
        if (tile < 7) {
            int trow0 = tbase + (tile + 1) * 32;
#pragma unroll
            for (int jj = 0; jj < 8; jj++) {
                int tpos = trow0 + w + 4 * jj;
                float4 val = make_float4(0.f, 0.f, 0.f, 0.f);
                if (tpos < t_total) {
                    const float* krow = (tpos == start_pos)
                        ? &g_k[(size_t)b * 1024 + h * HD]
                        : &cache_k[(((size_t)b * MAXSEQ + tpos) * NKV + h) * HD];
                    val = *(const float4*)(krow + lane * 4);
                }
                pre[jj] = val;
            }
        }
        // compute: warp w owns rows [w*8, w*8+8); lane handles rows
        // w*8+rowgrp and w*8+rowgrp+4 over its 16 dims, all 4 reps.
#pragma unroll
        for (int rr = 0; rr < 2; rr++) {
            int row = w * 8 + rowgrp + 4 * rr;
            float s0 = 0.f, s1 = 0.f, s2 = 0.f, s3 = 0.f;
#pragma unroll
            for (int qq = 0; qq < 4; qq++) {
                float4 k4 = *(const float4*)&ts[buf][row][(e + 8 * qq) * 4];
                s0 += k4.x * qreg[0][qq].x + k4.y * qreg[0][qq].y +
                      k4.z * qreg[0][qq].z + k4.w * qreg[0][qq].w;
                s1 += k4.x * qreg[1][qq].x + k4.y * qreg[1][qq].y +
                      k4.z * qreg[1][qq].z + k4.w * qreg[1][qq].w;
                s2 += k4.x * qreg[2][qq].x + k4.y * qreg[2][qq].y +
                      k4.z * qreg[2][qq].z + k4.w * qreg[2][qq].w;
                s3 += k4.x * qreg[3][qq].x + k4.y * qreg[3][qq].y +
                      k4.z * qreg[3][qq].z + k4.w * qreg[3][qq].w;
            }
#pragma unroll
            for (int off = 1; off < 8; off <<= 1) {
                s0 += __shfl_xor_sync(0xffffffffu, s0, off);
                s1 += __shfl_xor_sync(0xffffffffu, s1, off);
                s2 += __shfl_xor_sync(0xffffffffu, s2, off);
                s3 += __shfl_xor_sync(0xffffffffu, s3, off);
            }
            if (e == 0) {
                int tl = tile * 32 + row;
                bool valid = (tbase + tl) < t_total;
                *(float4*)&sc[tl][0] = valid
                    ? make_float4(s0, s1, s2, s3)
                    : make_float4(-INFINITY, -INFINITY, -INFINITY, -INFINITY);
            }
        }
        if (tile < 7) {
#pragma unroll
            for (int jj = 0; jj < 8; jj++)
                *(float4*)&ts[buf ^ 1][w + 4 * jj][lane * 4] = pre[jj];
        }
        __syncthreads();
        buf ^= 1;
    }

    // ======================= phase 2: partial softmax =======================
    {
        int r = w;
        float sv[NCHUNK];
        float m = -INFINITY;
#pragma unroll
        for (int i = 0; i < 8; i++) {
            sv[i] = sc[lane + 32 * i][r];
            m = fmaxf(m, sv[i]);
        }
#pragma unroll
        for (int off = 16; off > 0; off >>= 1)
            m = fmaxf(m, __shfl_xor_sync(0xffffffffu, m, off));
        float lsum = 0.f;
#pragma unroll
        for (int i = 0; i < 8; i++) {
            float p = (m == -INFINITY) ? 0.f : __expf(sv[i] - m);
            sc[lane + 32 * i][r] = p;
            lsum += p;
        }
#pragma unroll
        for (int off = 16; off > 0; off >>= 1)
            lsum += __shfl_xor_sync(0xffffffffu, lsum, off);
        if (lane == 0) {
            size_t mlidx = ((((size_t)b * NKV + h) * NREP + r) * NCHUNK + c) * 2;
            g_ml[mlidx]     = m;
            g_ml[mlidx + 1] = lsum;
        }
    }
    __syncthreads();

    // ======================= phase 3: P @ V (V stream) ======================
    // warp w handles rows [w*8, w*8+8) of each tile, all 4 reps; lane owns
    // d-quad lane. Cross-warp reduction via red[] at the end.
    float4 acc0 = make_float4(0.f, 0.f, 0.f, 0.f);
    float4 acc1 = acc0, acc2 = acc0, acc3 = acc0;

#pragma unroll
    for (int jj = 0; jj < 8; jj++) {
        int tpos = tbase + w + 4 * jj;
        float4 val = make_float4(0.f, 0.f, 0.f, 0.f);
        if (tpos < t_total) {
            const float* vrow = (tpos == start_pos)
                ? &g_v[(size_t)b * 1024 + h * HD]
                : &cache_v[(((size_t)b * MAXSEQ + tpos) * NKV + h) * HD];
            val = *(const float4*)(vrow + lane * 4);
        }
        pre[jj] = val;
    }
#pragma unroll
    for (int jj = 0; jj < 8; jj++)
        *(float4*)&ts[0][w + 4 * jj][lane * 4] = pre[jj];
    __syncthreads();

    buf = 0;
    for (int tile = 0; tile < 8; tile++) {
        if (tile < 7) {
            int trow0 = tbase + (tile + 1) * 32;
#pragma unroll
            for (int jj = 0; jj < 8; jj++) {
                int tpos = trow0 + w + 4 * jj;
                float4 val = make_float4(0.f, 0.f, 0.f, 0.f);
                if (tpos < t_total) {
                    const float* vrow = (tpos == start_pos)
                        ? &g_v[(size_t)b * 1024 + h * HD]
                        : &cache_v[(((size_t)b * MAXSEQ + tpos) * NKV + h) * HD];
                    val = *(const float4*)(vrow + lane * 4);
                }
                pre[jj] = val;
            }
        }
#pragma unroll
        for (int rr = 0; rr < 8; rr++) {
            int row = w * 8 + rr;
            float4 p  = *(const float4*)&sc[tile * 32 + row][0];
            float4 v4 = *(const float4*)&ts[buf][row][lane * 4];
            acc0.x += p.x * v4.x; acc0.y += p.x * v4.y; acc0.z += p.x * v4.z; acc0.w += p.x * v4.w;
            acc1.x += p.y * v4.x; acc1.y += p.y * v4.y; acc1.z += p.y * v4.z; acc1.w += p.y * v4.w;
            acc2.x += p.z * v4.x; acc2.y += p.z * v4.y; acc2.z += p.z * v4.z; acc2.w += p.z * v4.w;
            acc3.x += p.w * v4.x; acc3.y += p.w * v4.y; acc3.z += p.w * v4.z; acc3.w += p.w * v4.w;
        }
        if (tile < 7) {
#pragma unroll
            for (int jj = 0; jj < 8; jj++)
                *(float4*)&ts[buf ^ 1][w + 4 * jj][lane * 4] = pre[jj];
        }
        __syncthreads();
        buf ^= 1;
    }

    *(float4*)&red[w][0][lane * 4] = acc0;
    *(float4*)&red[w][1][lane * 4] = acc1;
    *(float4*)&red[w][2][lane * 4] = acc2;
    *(float4*)&red[w][3][lane * 4] = acc3;
    __syncthreads();

    for (int i = tid; i < 4 * HD; i += 128) {
        int r = i >> 7, d = i & 127;
        float v = red[0][r][d] + red[1][r][d] + red[2][r][d] + red[3][r][d];
        g_pout[(((((size_t)b * NKV + h) * NREP + r) * NCHUNK) + c) * HD + d] = v;
    }
}

// ------------------------- combine partial softmax --------------------------
__global__ __launch_bounds__(128) void combine_kernel()
{
    int blk = blockIdx.x;                 // r + 4*(h + 8*b)
    int r = blk & 3;
    int h = (blk >> 2) & 7;
    int b = blk >> 5;
    int d = threadIdx.x;

    size_t base = (((size_t)b * NKV + h) * NREP + r) * NCHUNK;

    float mm[NCHUNK], ll[NCHUNK];
    float mg = -INFINITY;
#pragma unroll
    for (int c = 0; c < NCHUNK; c++) {
        mm[c] = g_ml[(base + c) * 2];
        ll[c] = g_ml[(base + c) * 2 + 1];
        if (ll[c] > 0.f) mg = fmaxf(mg, mm[c]);
    }
    float L = 0.f, o = 0.f;
#pragma unroll
    for (int c = 0; c < NCHUNK; c++) {
        if (ll[c] > 0.f) {
            float f = __expf(mm[c] - mg);
            L += ll[c] * f;
            o += f * g_pout[(base + c) * HD + d];
        }
    }
    g_attn[(size_t)b * DIM + (h * NREP + r) * HD + d] = o / L;
}

// ------------------------- O-proj split-K reduce ----------------------------
__global__ void o_finish(float* __restrict__ out)
{
    int i = blockIdx.x * blockDim.x + threadIdx.x;  // 32768 float4 elems
    if (i >= NB * DIM / 4) return;
    float4 s = make_float4(0.f, 0.f, 0.f, 0.f);
#pragma unroll
    for (int p = 0; p < O_SPLIT; p++) {
        float4 v = *((const float4*)&g_part[(size_t)p * NB * DIM] + i);
        s.x += v.x; s.y += v.y; s.z += v.z; s.w += v.w;
    }
    ((float4*)out)[i] = s;
}

// ------------------------- launcher -----------------------------------------
extern "C" void kernel_launch(void* const* d_in, const int* in_sizes, int n_in,
                              void* d_out, int out_size)
{
    const float* x  = (const float*)d_in[0];
    const float* fc = (const float*)d_in[1];
    const float* fs = (const float*)d_in[2];
    const float* wq = (const float*)d_in[3];
    const float* wk = (const float*)d_in[4];
    const float* wv = (const float*)d_in[5];
    const float* wo = (const float*)d_in[6];
    const float* ck = (const float*)d_in[7];
    const float* cv = (const float*)d_in[8];
    const int*   sp = (const int*)d_in[9];
    float* out = (float*)d_out;

    // QKV projection: 48 n-slabs x split 16 = 768 blocks
    proj_mma<<<48 * QKV_SPLIT, 128>>>(x, wq, wk, wv, 48, 4096, 5120,
                                      4096 / QKV_SPLIT, 6144);
    qkv_finish<<<384, 256>>>(fc, fs);
    attn_kernel<<<2048, 128>>>(ck, cv, sp);
    combine_kernel<<<1024, 128>>>();
    // O projection: 32 n-slabs x split 16 = 512 blocks
    proj_mma<<<32 * O_SPLIT, 128>>>(nullptr, wo, wo, wo, 32, 4096, 8192,
                                    4096 / O_SPLIT, 4096);
    o_finish<<<128, 256>>>(out);
}

// round 10
// speedup vs baseline: 1.8185x; 1.0612x over previous
#include <cuda_runtime.h>
#include <cuda_bf16.h>
#include <cstdint>
#include <math.h>

#define NB 32
#define DIM 4096
#define NKV 8
#define NREP 4
#define HD 128
#define MAXSEQ 2048
#define NCHUNK 8
#define CHUNK 256
#define QKV_SPLIT 16
#define O_SPLIT 16
#define TSS 132   // tile row stride (floats)

// ------------------------- device scratch (no allocs allowed) ---------------
__device__ float g_q[NB * DIM];                          // rope'd Q
__device__ float g_k[NB * NKV * HD];                     // rope'd new K row
__device__ float g_v[NB * NKV * HD];                     // new V row
__device__ float g_attn[NB * DIM];                       // attention output
__device__ float g_part[QKV_SPLIT * NB * 6144];          // split-K partials
__device__ float g_pout[NB * NKV * NCHUNK * 4 * NREP * HD];  // per-warp partials
__device__ float g_ml[NB * NKV * NREP * NCHUNK * 2];     // (m, l) per chunk

// ------------------------- bf16x3 MMA projection GEMM -----------------------
#define MMA_B16(acc, A0, A1, A2, A3, B0, B1)                                   \
    asm volatile(                                                              \
        "mma.sync.aligned.m16n8k16.row.col.f32.bf16.bf16.f32 "                 \
        "{%0,%1,%2,%3}, {%4,%5,%6,%7}, {%8,%9}, {%0,%1,%2,%3};"                \
        : "+f"(acc[0]), "+f"(acc[1]), "+f"(acc[2]), "+f"(acc[3])               \
        : "r"(A0), "r"(A1), "r"(A2), "r"(A3), "r"(B0), "r"(B1))

__device__ __forceinline__ void bf16_split(float v, unsigned& hbits, unsigned& lbits)
{
    __nv_bfloat16 h = __float2bfloat16_rn(v);
    float r = v - __bfloat162float(h);
    __nv_bfloat16 lo = __float2bfloat16_rn(r);
    hbits = (unsigned)__bfloat16_as_ushort(h);
    lbits = (unsigned)__bfloat16_as_ushort(lo);
}

__global__ __launch_bounds__(128) void proj_mma(
    const float* __restrict__ A,   // NB x 4096 (nullptr -> g_attn)
    const float* __restrict__ W0,
    const float* __restrict__ W1,
    const float* __restrict__ W2,
    int njb, int r1, int r2, int klen, int totalj)
{
    __shared__ unsigned sB[16 * 4 * 144];   // 36 KB
    __shared__ unsigned sAh[2 * 4 * 132];   // 4.2 KB
    __shared__ unsigned sAl[2 * 4 * 132];   // 4.2 KB

    const float* Ap = A ? A : g_attn;

    int jb    = blockIdx.x % njb;
    int split = blockIdx.x / njb;
    int j0    = jb * 128;

    const float* W;
    int jw;
    if (j0 < r1)      { W = W0; jw = j0; }
    else if (j0 < r2) { W = W1; jw = j0 - r1; }
    else              { W = W2; jw = j0 - r2; }

    int tid = threadIdx.x;
    int w   = tid >> 5, l = tid & 31;

    float acc[2][4][4];
#pragma unroll
    for (int i = 0; i < 2; i++)
#pragma unroll
        for (int j = 0; j < 4; j++)
#pragma unroll
            for (int c = 0; c < 4; c++) acc[i][j][c] = 0.f;

    int k0 = split * klen;
    int ksw   = l >> 3;
    int prw   = (l >> 2) & 1;
    int lq    = l & 3;

    for (int kc = k0; kc < k0 + klen; kc += 64) {
        __syncthreads();
#pragma unroll 4
        for (int rr = 0; rr < 32; rr++) {
            int n = w * 32 + rr;
            float2 v = *(const float2*)(W + (size_t)(jw + n) * 4096 + kc + 2 * l);
            unsigned h0, l0, h1, l1;
            bf16_split(v.x, h0, l0);
            bf16_split(v.y, h1, l1);
            unsigned uh = (h1 << 16) | h0;
            unsigned ul = (l1 << 16) | l0;
            int nt = n >> 3;
            int lanep = ((n & 7) << 2) + lq;
            *(uint2*)&sB[((nt * 4 + ksw) * 144) + lanep * 4 + prw * 2] =
                make_uint2(uh, ul);
        }
#pragma unroll
        for (int rr = 0; rr < 8; rr++) {
            int m = w * 8 + rr;
            float2 v = *(const float2*)(Ap + (size_t)m * 4096 + kc + 2 * l);
            unsigned h0, l0, h1, l1;
            bf16_split(v.x, h0, l0);
            bf16_split(v.y, h1, l1);
            unsigned uh = (h1 << 16) | h0;
            unsigned ul = (l1 << 16) | l0;
            int mt = m >> 4;
            int lanep = ((m & 7) << 2) + lq;
            int anum  = ((m >> 3) & 1) | (prw << 1);
            int idx = (mt * 4 + ksw) * 132 + lanep * 4 + anum;
            sAh[idx] = uh;
            sAl[idx] = ul;
        }
        __syncthreads();

#pragma unroll
        for (int ks = 0; ks < 4; ks++) {
            uint4 ah0 = *(const uint4*)&sAh[(ks) * 132 + l * 4];
            uint4 al0 = *(const uint4*)&sAl[(ks) * 132 + l * 4];
            uint4 ah1 = *(const uint4*)&sAh[(4 + ks) * 132 + l * 4];
            uint4 al1 = *(const uint4*)&sAl[(4 + ks) * 132 + l * 4];
#pragma unroll
            for (int ntl = 0; ntl < 4; ntl++) {
                uint4 bb = *(const uint4*)&sB[((w * 4 + ntl) * 4 + ks) * 144 + l * 4];
                MMA_B16(acc[0][ntl], ah0.x, ah0.y, ah0.z, ah0.w, bb.x, bb.z);
                MMA_B16(acc[1][ntl], ah1.x, ah1.y, ah1.z, ah1.w, bb.x, bb.z);
                MMA_B16(acc[0][ntl], al0.x, al0.y, al0.z, al0.w, bb.x, bb.z);
                MMA_B16(acc[1][ntl], al1.x, al1.y, al1.z, al1.w, bb.x, bb.z);
                MMA_B16(acc[0][ntl], ah0.x, ah0.y, ah0.z, ah0.w, bb.y, bb.w);
                MMA_B16(acc[1][ntl], ah1.x, ah1.y, ah1.z, ah1.w, bb.y, bb.w);
            }
        }
    }

    size_t pbase = (size_t)split * NB * totalj;
#pragma unroll
    for (int mt = 0; mt < 2; mt++)
#pragma unroll
        for (int ntl = 0; ntl < 4; ntl++) {
            int m = mt * 16 + (l >> 2);
            int j = j0 + ((w * 4 + ntl) << 3) + (lq << 1);
            *(float2*)&g_part[pbase + (size_t)m * totalj + j] =
                make_float2(acc[mt][ntl][0], acc[mt][ntl][1]);
            *(float2*)&g_part[pbase + (size_t)(m + 8) * totalj + j] =
                make_float2(acc[mt][ntl][2], acc[mt][ntl][3]);
        }
}

// ------------------------- split-K reduce + RoPE ----------------------------
__global__ void qkv_finish(const float* __restrict__ fc, const float* __restrict__ fs)
{
    int p = blockIdx.x * blockDim.x + threadIdx.x;
    if (p >= NB * 3072) return;
    int b = p / 3072;
    int j = (p % 3072) * 2;

    float v0 = 0.f, v1 = 0.f;
#pragma unroll
    for (int s = 0; s < QKV_SPLIT; s++) {
        size_t base = (size_t)s * NB * 6144 + (size_t)b * 6144 + j;
        v0 += g_part[base];
        v1 += g_part[base + 1];
    }

    if (j < 5120) {
        int pi = (j & 127) >> 1;
        float c = fc[pi], s = fs[pi];
        float o0 = v0 * c - v1 * s;
        float o1 = v0 * s + v1 * c;
        if (j < 4096) {
            g_q[b * DIM + j]     = o0;
            g_q[b * DIM + j + 1] = o1;
        } else {
            g_k[b * 1024 + j - 4096]     = o0;
            g_k[b * 1024 + j - 4096 + 1] = o1;
        }
    } else {
        g_v[b * 1024 + j - 5120]     = v0;
        g_v[b * 1024 + j - 5120 + 1] = v1;
    }
}

// ------------------------- cp.async helpers ---------------------------------
__device__ __forceinline__ void cp16(unsigned dst, const float* src)
{
    asm volatile("cp.async.cg.shared.global [%0], [%1], 16;"
                 :: "r"(dst), "l"(src) : "memory");
}
#define CP_COMMIT() asm volatile("cp.async.commit_group;" ::: "memory")
#define CP_WAIT1()  asm volatile("cp.async.wait_group 1;" ::: "memory")
#define CP_WAIT0()  asm volatile("cp.async.wait_group 0;" ::: "memory")

// ------------------------- flash-decode attention ---------------------------
// One block per (b, kv_head, chunk). 128 threads = 4 warps.
// Q in registers; K/V staged via cp.async (double-buffered, no staging regs);
// per-warp phase-3 partials go straight to g_pout (no cross-warp smem red).
__global__ __launch_bounds__(128, 5) void attn_kernel(
    const float* __restrict__ cache_k, const float* __restrict__ cache_v,
    const int* __restrict__ sp)
{
    int blk = blockIdx.x;                 // c + 8*(h + 8*b)
    int c = blk & 7;
    int h = (blk >> 3) & 7;
    int b = blk >> 6;

    int tid = threadIdx.x;
    int w = tid >> 5, lane = tid & 31;
    int rowgrp = lane >> 3;               // 0..3
    int e      = lane & 7;                // dim-eighth

    int start_pos = *sp;
    int t_total = start_pos + 1;

    __shared__ float ts[2][32][TSS];      // staged K/V tiles, 33.8KB
    __shared__ float sc[CHUNK][4];        // scores -> probs, 4KB

    unsigned ts_smem = (unsigned)__cvta_generic_to_shared(&ts[0][0][0]);

    const float scale = 0.08838834764831845f;  // 1/sqrt(128)

    // Q in registers: qreg[rep][qq] over dims quads e+8*qq
    float4 qreg[4][4];
#pragma unroll
    for (int r = 0; r < 4; r++)
#pragma unroll
        for (int qq = 0; qq < 4; qq++) {
            float4 v = *(const float4*)&g_q[(size_t)b * DIM + (h * NREP + r) * HD +
                                            (e + 8 * qq) * 4];
            qreg[r][qq] = make_float4(v.x * scale, v.y * scale,
                                      v.z * scale, v.w * scale);
        }

    int tbase = c * CHUNK;
    const float* knew = &g_k[(size_t)b * 1024 + h * HD];
    const float* vnew = &g_v[(size_t)b * 1024 + h * HD];

    // ======================= phase 1: scores (K stream) =====================
    // stage tile 0
    {
#pragma unroll
        for (int jj = 0; jj < 8; jj++) {
            int row = w + 4 * jj;
            int tpos = tbase + row;
            int tp = tpos < start_pos ? tpos : start_pos;
            const float* src = (tp == start_pos)
                ? knew : &cache_k[(((size_t)b * MAXSEQ + tp) * NKV + h) * HD];
            cp16(ts_smem + (unsigned)(row * TSS + lane * 4) * 4, src + lane * 4);
        }
        CP_COMMIT();
    }

    int buf = 0;
    for (int tile = 0; tile < 8; tile++) {
        if (tile < 7) {
            int trow0 = tbase + (tile + 1) * 32;
            unsigned bofs = ts_smem + (unsigned)((buf ^ 1) * 32 * TSS) * 4;
#pragma unroll
            for (int jj = 0; jj < 8; jj++) {
                int row = w + 4 * jj;
                int tpos = trow0 + row;
                int tp = tpos < start_pos ? tpos : start_pos;
                const float* src = (tp == start_pos)
                    ? knew : &cache_k[(((size_t)b * MAXSEQ + tp) * NKV + h) * HD];
                cp16(bofs + (unsigned)(row * TSS + lane * 4) * 4, src + lane * 4);
            }
            CP_COMMIT();
            CP_WAIT1();
        } else {
            CP_WAIT0();
        }
        __syncthreads();

        // compute: warp w owns rows [w*8, w*8+8); lane handles rows
        // w*8+rowgrp and w*8+rowgrp+4 over its 16 dims, all 4 reps.
#pragma unroll
        for (int rr = 0; rr < 2; rr++) {
            int row = w * 8 + rowgrp + 4 * rr;
            float s0 = 0.f, s1 = 0.f, s2 = 0.f, s3 = 0.f;
#pragma unroll
            for (int qq = 0; qq < 4; qq++) {
                float4 k4 = *(const float4*)&ts[buf][row][(e + 8 * qq) * 4];
                s0 += k4.x * qreg[0][qq].x + k4.y * qreg[0][qq].y +
                      k4.z * qreg[0][qq].z + k4.w * qreg[0][qq].w;
                s1 += k4.x * qreg[1][qq].x + k4.y * qreg[1][qq].y +
                      k4.z * qreg[1][qq].z + k4.w * qreg[1][qq].w;
                s2 += k4.x * qreg[2][qq].x + k4.y * qreg[2][qq].y +
                      k4.z * qreg[2][qq].z + k4.w * qreg[2][qq].w;
                s3 += k4.x * qreg[3][qq].x + k4.y * qreg[3][qq].y +
                      k4.z * qreg[3][qq].z + k4.w * qreg[3][qq].w;
            }
#pragma unroll
            for (int off = 1; off < 8; off <<= 1) {
                s0 += __shfl_xor_sync(0xffffffffu, s0, off);
                s1 += __shfl_xor_sync(0xffffffffu, s1, off);
                s2 += __shfl_xor_sync(0xffffffffu, s2, off);
                s3 += __shfl_xor_sync(0xffffffffu, s3, off);
            }
            if (e == 0) {
                int tl = tile * 32 + row;
                bool valid = (tbase + tl) < t_total;
                *(float4*)&sc[tl][0] = valid
                    ? make_float4(s0, s1, s2, s3)
                    : make_float4(-INFINITY, -INFINITY, -INFINITY, -INFINITY);
            }
        }
        __syncthreads();
        buf ^= 1;
    }

    // ======================= phase 2: partial softmax =======================
    {
        int r = w;
        float sv[NCHUNK];
        float m = -INFINITY;
#pragma unroll
        for (int i = 0; i < 8; i++) {
            sv[i] = sc[lane + 32 * i][r];
            m = fmaxf(m, sv[i]);
        }
#pragma unroll
        for (int off = 16; off > 0; off >>= 1)
            m = fmaxf(m, __shfl_xor_sync(0xffffffffu, m, off));
        float lsum = 0.f;
#pragma unroll
        for (int i = 0; i < 8; i++) {
            float p = (m == -INFINITY) ? 0.f : __expf(sv[i] - m);
            sc[lane + 32 * i][r] = p;
            lsum += p;
        }
#pragma unroll
        for (int off = 16; off > 0; off >>= 1)
            lsum += __shfl_xor_sync(0xffffffffu, lsum, off);
        if (lane == 0) {
            size_t mlidx = ((((size_t)b * NKV + h) * NREP + r) * NCHUNK + c) * 2;
            g_ml[mlidx]     = m;
            g_ml[mlidx + 1] = lsum;
        }
    }
    __syncthreads();

    // ======================= phase 3: P @ V (V stream) ======================
    // warp w handles rows [w*8, w*8+8), all 4 reps; lane owns d-quad lane.
    float4 acc0 = make_float4(0.f, 0.f, 0.f, 0.f);
    float4 acc1 = acc0, acc2 = acc0, acc3 = acc0;

    {
#pragma unroll
        for (int jj = 0; jj < 8; jj++) {
            int row = w + 4 * jj;
            int tpos = tbase + row;
            int tp = tpos < start_pos ? tpos : start_pos;
            const float* src = (tp == start_pos)
                ? vnew : &cache_v[(((size_t)b * MAXSEQ + tp) * NKV + h) * HD];
            cp16(ts_smem + (unsigned)(row * TSS + lane * 4) * 4, src + lane * 4);
        }
        CP_COMMIT();
    }

    buf = 0;
    for (int tile = 0; tile < 8; tile++) {
        if (tile < 7) {
            int trow0 = tbase + (tile + 1) * 32;
            unsigned bofs = ts_smem + (unsigned)((buf ^ 1) * 32 * TSS) * 4;
#pragma unroll
            for (int jj = 0; jj < 8; jj++) {
                int row = w + 4 * jj;
                int tpos = trow0 + row;
                int tp = tpos < start_pos ? tpos : start_pos;
                const float* src = (tp == start_pos)
                    ? vnew : &cache_v[(((size_t)b * MAXSEQ + tp) * NKV + h) * HD];
                cp16(bofs + (unsigned)(row * TSS + lane * 4) * 4, src + lane * 4);
            }
            CP_COMMIT();
            CP_WAIT1();
        } else {
            CP_WAIT0();
        }
        __syncthreads();

#pragma unroll
        for (int rr = 0; rr < 8; rr++) {
            int row = w * 8 + rr;
            float4 p  = *(const float4*)&sc[tile * 32 + row][0];
            float4 v4 = *(const float4*)&ts[buf][row][lane * 4];
            acc0.x += p.x * v4.x; acc0.y += p.x * v4.y; acc0.z += p.x * v4.z; acc0.w += p.x * v4.w;
            acc1.x += p.y * v4.x; acc1.y += p.y * v4.y; acc1.z += p.y * v4.z; acc1.w += p.y * v4.w;
            acc2.x += p.z * v4.x; acc2.y += p.z * v4.y; acc2.z += p.z * v4.z; acc2.w += p.z * v4.w;
            acc3.x += p.w * v4.x; acc3.y += p.w * v4.y; acc3.z += p.w * v4.z; acc3.w += p.w * v4.w;
        }
        __syncthreads();
        buf ^= 1;
    }

    // per-warp partials: [b][h][c][warp][rep][HD]
    size_t obase = ((((size_t)(b * NKV + h) * NCHUNK + c) * 4 + w) * NREP) * HD;
    *(float4*)&g_pout[obase + 0 * HD + lane * 4] = acc0;
    *(float4*)&g_pout[obase + 1 * HD + lane * 4] = acc1;
    *(float4*)&g_pout[obase + 2 * HD + lane * 4] = acc2;
    *(float4*)&g_pout[obase + 3 * HD + lane * 4] = acc3;
}

// ------------------------- combine partial softmax --------------------------
__global__ __launch_bounds__(128) void combine_kernel()
{
    int blk = blockIdx.x;                 // r + 4*(h + 8*b)
    int r = blk & 3;
    int h = (blk >> 2) & 7;
    int b = blk >> 5;
    int d = threadIdx.x;

    size_t mlb = (((size_t)b * NKV + h) * NREP + r) * NCHUNK;

    float mm[NCHUNK], ll[NCHUNK];
    float mg = -INFINITY;
#pragma unroll
    for (int c = 0; c < NCHUNK; c++) {
        mm[c] = g_ml[(mlb + c) * 2];
        ll[c] = g_ml[(mlb + c) * 2 + 1];
        if (ll[c] > 0.f) mg = fmaxf(mg, mm[c]);
    }
    float L = 0.f, o = 0.f;
#pragma unroll
    for (int c = 0; c < NCHUNK; c++) {
        if (ll[c] > 0.f) {
            float f = __expf(mm[c] - mg);
            L += ll[c] * f;
            size_t pb = ((((size_t)(b * NKV + h) * NCHUNK + c) * 4) * NREP + r) * HD + d;
            float s = g_pout[pb] + g_pout[pb + NREP * HD] +
                      g_pout[pb + 2 * NREP * HD] + g_pout[pb + 3 * NREP * HD];
            o += f * s;
        }
    }
    g_attn[(size_t)b * DIM + (h * NREP + r) * HD + d] = o / L;
}

// ------------------------- O-proj split-K reduce ----------------------------
__global__ void o_finish(float* __restrict__ out)
{
    int i = blockIdx.x * blockDim.x + threadIdx.x;  // 32768 float4 elems
    if (i >= NB * DIM / 4) return;
    float4 s = make_float4(0.f, 0.f, 0.f, 0.f);
#pragma unroll
    for (int p = 0; p < O_SPLIT; p++) {
        float4 v = *((const float4*)&g_part[(size_t)p * NB * DIM] + i);
        s.x += v.x; s.y += v.y; s.z += v.z; s.w += v.w;
    }
    ((float4*)out)[i] = s;
}

// ------------------------- launcher -----------------------------------------
extern "C" void kernel_launch(void* const* d_in, const int* in_sizes, int n_in,
                              void* d_out, int out_size)
{
    const float* x  = (const float*)d_in[0];
    const float* fc = (const float*)d_in[1];
    const float* fs = (const float*)d_in[2];
    const float* wq = (const float*)d_in[3];
    const float* wk = (const float*)d_in[4];
    const float* wv = (const float*)d_in[5];
    const float* wo = (const float*)d_in[6];
    const float* ck = (const float*)d_in[7];
    const float* cv = (const float*)d_in[8];
    const int*   sp = (const int*)d_in[9];
    float* out = (float*)d_out;

    // QKV projection: 48 n-slabs x split 16 = 768 blocks
    proj_mma<<<48 * QKV_SPLIT, 128>>>(x, wq, wk, wv, 48, 4096, 5120,
                                      4096 / QKV_SPLIT, 6144);
    qkv_finish<<<384, 256>>>(fc, fs);
    attn_kernel<<<2048, 128>>>(ck, cv, sp);
    combine_kernel<<<1024, 128>>>();
    // O projection: 32 n-slabs x split 16 = 512 blocks
    proj_mma<<<32 * O_SPLIT, 128>>>(nullptr, wo, wo, wo, 32, 4096, 8192,
                                    4096 / O_SPLIT, 4096);
    o_finish<<<128, 256>>>(out);
}